// round 4
// baseline (speedup 1.0000x reference)
#include <cuda_runtime.h>
#include <cuda_fp16.h>
#include <math.h>

#define N_NODES 20000
#define N_EDGES 400000
#define DIM 128
#define NB 16
#define ZD 16
#define UW (NB*DIM)   // 2048

// ---------------- device scratch (static, no allocations) ----------------
__device__ float  g_zi16[N_NODES*ZD];
__device__ float  g_zi[N_NODES*DIM];
__device__ float  g_zself[N_NODES*DIM];
__device__ float  g_h[N_NODES*DIM];
__device__ __half g_Uh[(size_t)N_NODES*UW];     // U[n][b][d] fp16
__device__ __half g_Vth[DIM*UW];                // V^T fp16 (K x NB*DIM)
__device__ __half g_zih[N_NODES*DIM];           // fp16 copy of activations
__device__ float  g_mij[(size_t)N_EDGES*DIM];   // per-edge messages (src-rank order)

// CSR scratch
__device__ int g_degD[N_NODES], g_offD[N_NODES+1], g_curD[N_NODES], g_eidD[N_EDGES];
__device__ int g_degS[N_NODES], g_offS[N_NODES+1], g_curS[N_NODES];
__device__ int g_rank[N_EDGES];

__device__ __forceinline__ float silu_f(float x) {
    return x / (1.0f + __expf(-x));
}

// ---------------- small kernels ----------------
__global__ void k_embed(const int* __restrict__ species, const float* __restrict__ Z) {
    int t = blockIdx.x * blockDim.x + threadIdx.x;
    if (t < N_NODES * ZD) {
        int n = t >> 4, k = t & 15;
        g_zi16[t] = Z[species[n] * ZD + k];
    }
}

__global__ void k_transpose(const float* __restrict__ V, int K) {
    int t = blockIdx.x * blockDim.x + threadIdx.x;
    if (t < K * UW) {
        int j = t % UW;
        int k = t / UW;
        int b = j >> 7, d = j & 127;
        g_Vth[t] = __float2half(V[((size_t)b * K + k) * DIM + d]);
    }
}

__global__ void k_f2h(const float* __restrict__ src, __half* __restrict__ dst, int n) {
    int t = blockIdx.x * blockDim.x + threadIdx.x;
    if (t < n) dst[t] = __float2half(src[t]);
}

__global__ void k_copy0(float* __restrict__ out) {
    int t = blockIdx.x * blockDim.x + threadIdx.x;
    if (t < N_NODES * DIM) {
        int n = t >> 7, d = t & 127;
        out[N_NODES * DIM + n * 2 * DIM + d] = g_zi[t];
    }
}

__global__ void k_copy1(float* __restrict__ out) {
    int t = blockIdx.x * blockDim.x + threadIdx.x;
    if (t < N_NODES * DIM) {
        int n = t >> 7, d = t & 127;
        float v = g_zi[t];
        out[t] = v;
        out[N_NODES * DIM + n * 2 * DIM + DIM + d] = v;
    }
}

// ---------------- CSR build ----------------
__global__ void k_zero_deg() {
    int t = blockIdx.x * blockDim.x + threadIdx.x;
    if (t < N_NODES) { g_degD[t] = 0; g_degS[t] = 0; }
}
__global__ void k_count2(const int* __restrict__ edst, const int* __restrict__ esrc) {
    int e = blockIdx.x * blockDim.x + threadIdx.x;
    if (e < N_EDGES) {
        atomicAdd(&g_degD[edst[e]], 1);
        atomicAdd(&g_degS[esrc[e]], 1);
    }
}
__global__ void k_scan(const int* __restrict__ deg, int* __restrict__ off,
                       int* __restrict__ cur) {   // single block, 256 threads
    __shared__ int ps[256];
    const int t = threadIdx.x;
    const int CH = (N_NODES + 255) / 256;
    int base = t * CH;
    int s = 0;
    for (int i = 0; i < CH; i++) {
        int idx = base + i;
        if (idx < N_NODES) s += deg[idx];
    }
    ps[t] = s;
    __syncthreads();
    for (int d = 1; d < 256; d <<= 1) {
        int v = (t >= d) ? ps[t - d] : 0;
        __syncthreads();
        ps[t] += v;
        __syncthreads();
    }
    int run = (t > 0) ? ps[t - 1] : 0;
    for (int i = 0; i < CH; i++) {
        int idx = base + i;
        if (idx < N_NODES) {
            off[idx] = run;
            cur[idx] = run;
            run += deg[idx];
        }
    }
    if (t == 255) off[N_NODES] = ps[255];
}
__global__ void k_fillD(const int* __restrict__ edst) {
    int e = blockIdx.x * blockDim.x + threadIdx.x;
    if (e < N_EDGES) {
        int pos = atomicAdd(&g_curD[edst[e]], 1);
        g_eidD[pos] = e;
    }
}
__global__ void k_fillS(const int* __restrict__ esrc) {
    int e = blockIdx.x * blockDim.x + threadIdx.x;
    if (e < N_EDGES) {
        int pos = atomicAdd(&g_curS[esrc[e]], 1);
        g_rank[e] = pos;
    }
}

// ---------------- fp32 SGEMM (zself + onsite), BM=BN=128, 8x8/thread ------
template<int OUTHALF>
__global__ __launch_bounds__(256, 2) void k_gemm2(
    const float* __restrict__ A, const float* __restrict__ B,
    const float* __restrict__ bias, const float* __restrict__ Cadd,
    void* __restrict__ Cv,
    int M, int K, int lda, int ldb, int ldc, int act)
{
    __shared__ float As[16][136];
    __shared__ float Bs[16][128];

    const int t    = threadIdx.x;
    const int warp = t >> 5, lane = t & 31;
    const int wr = warp & 3, wc = warp >> 2;
    const int lr = lane >> 3, lc = lane & 7;
    const int row0 = wr * 32 + lr * 8;
    const int col0 = wc * 64 + lc * 8;
    const int m0 = blockIdx.y * 128, n0 = blockIdx.x * 128;

    const int arow = t >> 1;
    const int ak   = (t & 1) * 8;
    const int brow = t >> 4;
    const int bcol = (t & 15) * 8;

    float acc[8][8];
    #pragma unroll
    for (int i = 0; i < 8; i++)
        #pragma unroll
        for (int j = 0; j < 8; j++) acc[i][j] = 0.0f;

    for (int k0 = 0; k0 < K; k0 += 16) {
        float4 a0 = make_float4(0.f,0.f,0.f,0.f), a1 = a0;
        const int gm = m0 + arow;
        if (gm < M) {
            a0 = *(const float4*)&A[(size_t)gm * lda + k0 + ak];
            a1 = *(const float4*)&A[(size_t)gm * lda + k0 + ak + 4];
        }
        float4 b0 = *(const float4*)&B[(size_t)(k0 + brow) * ldb + n0 + bcol];
        float4 b1 = *(const float4*)&B[(size_t)(k0 + brow) * ldb + n0 + bcol + 4];

        __syncthreads();
        As[ak+0][arow] = a0.x; As[ak+1][arow] = a0.y;
        As[ak+2][arow] = a0.z; As[ak+3][arow] = a0.w;
        As[ak+4][arow] = a1.x; As[ak+5][arow] = a1.y;
        As[ak+6][arow] = a1.z; As[ak+7][arow] = a1.w;
        *(float4*)&Bs[brow][bcol]     = b0;
        *(float4*)&Bs[brow][bcol + 4] = b1;
        __syncthreads();

        #pragma unroll
        for (int kk = 0; kk < 16; kk++) {
            float4 x0 = *(float4*)&As[kk][row0];
            float4 x1 = *(float4*)&As[kk][row0 + 4];
            float4 y0 = *(float4*)&Bs[kk][col0];
            float4 y1 = *(float4*)&Bs[kk][col0 + 4];
            float ar[8] = {x0.x,x0.y,x0.z,x0.w,x1.x,x1.y,x1.z,x1.w};
            float br[8] = {y0.x,y0.y,y0.z,y0.w,y1.x,y1.y,y1.z,y1.w};
            #pragma unroll
            for (int i = 0; i < 8; i++)
                #pragma unroll
                for (int j = 0; j < 8; j++)
                    acc[i][j] += ar[i] * br[j];
        }
    }

    float bv[8];
    #pragma unroll
    for (int j = 0; j < 8; j++) bv[j] = bias ? bias[n0 + col0 + j] : 0.0f;

    #pragma unroll
    for (int i = 0; i < 8; i++) {
        int m = m0 + row0 + i;
        if (m >= M) continue;
        float v[8];
        #pragma unroll
        for (int j = 0; j < 8; j++) {
            float x = acc[i][j] + bv[j];
            if (act) x = silu_f(x);
            v[j] = x;
        }
        if (Cadd) {
            const float4* rp = (const float4*)&Cadd[(size_t)m * ldc + n0 + col0];
            float4 r0 = rp[0], r1 = rp[1];
            v[0]+=r0.x; v[1]+=r0.y; v[2]+=r0.z; v[3]+=r0.w;
            v[4]+=r1.x; v[5]+=r1.y; v[6]+=r1.z; v[7]+=r1.w;
        }
        if (OUTHALF) {
            __half2* cp = (__half2*)((__half*)Cv + (size_t)m * ldc + n0 + col0);
            cp[0] = __floats2half2_rn(v[0], v[1]);
            cp[1] = __floats2half2_rn(v[2], v[3]);
            cp[2] = __floats2half2_rn(v[4], v[5]);
            cp[3] = __floats2half2_rn(v[6], v[7]);
        } else {
            float* cp = (float*)Cv + (size_t)m * ldc + n0 + col0;
            ((float4*)cp)[0] = make_float4(v[0], v[1], v[2], v[3]);
            ((float4*)cp)[1] = make_float4(v[4], v[5], v[6], v[7]);
        }
    }
}

// ---------------- fp16 tensor-core GEMM (U-GEMM): C_h = A_h @ B_h ---------
__global__ __launch_bounds__(256, 2) void k_hgemm(
    const __half* __restrict__ A, const __half* __restrict__ B,
    __half* __restrict__ C, int M, int K, int ldb)
{
    __shared__ __half As[128][40];
    __shared__ __half Bs[32][136];

    const int t    = threadIdx.x;
    const int warp = t >> 5, lane = t & 31;
    const int wm = (warp & 3) * 32;
    const int wn = (warp >> 2) * 64;
    const int m0 = blockIdx.y * 128, n0 = blockIdx.x * 128;

    const int arow = t >> 1, ak = (t & 1) * 8;
    const int brow = t >> 4, bcol = (t & 15) * 8;

    float acc[2][8][4];
    #pragma unroll
    for (int mt = 0; mt < 2; mt++)
        #pragma unroll
        for (int nt = 0; nt < 8; nt++)
            #pragma unroll
            for (int i = 0; i < 4; i++) acc[mt][nt][i] = 0.0f;

    const uint4 z4 = make_uint4(0,0,0,0);

    for (int k0 = 0; k0 < K; k0 += 32) {
        const int nsub = (K - k0 >= 32) ? 2 : 1;
        uint4 av0 = z4, av1 = z4, bv0, bv1;
        const int gm = m0 + arow;
        if (gm < M) {
            av0 = *(const uint4*)&A[(size_t)gm * K + k0 + ak];
            if (nsub == 2) av1 = *(const uint4*)&A[(size_t)gm * K + k0 + 16 + ak];
        }
        bv0 = *(const uint4*)&B[(size_t)(k0 + brow) * ldb + n0 + bcol];
        if (nsub == 2) bv1 = *(const uint4*)&B[(size_t)(k0 + 16 + brow) * ldb + n0 + bcol];

        __syncthreads();
        *(uint4*)&As[arow][ak] = av0;
        if (nsub == 2) *(uint4*)&As[arow][16 + ak] = av1;
        *(uint4*)&Bs[brow][bcol] = bv0;
        if (nsub == 2) *(uint4*)&Bs[16 + brow][bcol] = bv1;
        __syncthreads();

        #pragma unroll
        for (int sub = 0; sub < 2; sub++) {
            if (sub >= nsub) break;
            const int kc = sub * 16;

            unsigned af[2][4];
            #pragma unroll
            for (int mt = 0; mt < 2; mt++) {
                const __half* p = &As[wm + mt*16 + (lane & 15)][kc + ((lane >> 4) << 3)];
                unsigned addr = (unsigned)__cvta_generic_to_shared(p);
                asm volatile("ldmatrix.sync.aligned.m8n8.x4.shared.b16 {%0,%1,%2,%3}, [%4];"
                    : "=r"(af[mt][0]), "=r"(af[mt][1]), "=r"(af[mt][2]), "=r"(af[mt][3])
                    : "r"(addr));
            }
            unsigned bf[8][2];
            #pragma unroll
            for (int q = 0; q < 4; q++) {
                const __half* p = &Bs[kc + (lane & 15)][wn + q*16 + ((lane >> 4) << 3)];
                unsigned addr = (unsigned)__cvta_generic_to_shared(p);
                asm volatile("ldmatrix.sync.aligned.m8n8.x4.trans.shared.b16 {%0,%1,%2,%3}, [%4];"
                    : "=r"(bf[q*2][0]), "=r"(bf[q*2][1]), "=r"(bf[q*2+1][0]), "=r"(bf[q*2+1][1])
                    : "r"(addr));
            }
            #pragma unroll
            for (int mt = 0; mt < 2; mt++)
                #pragma unroll
                for (int nt = 0; nt < 8; nt++) {
                    asm volatile(
                        "mma.sync.aligned.m16n8k16.row.col.f32.f16.f16.f32 "
                        "{%0,%1,%2,%3}, {%4,%5,%6,%7}, {%8,%9}, {%0,%1,%2,%3};"
                        : "+f"(acc[mt][nt][0]), "+f"(acc[mt][nt][1]),
                          "+f"(acc[mt][nt][2]), "+f"(acc[mt][nt][3])
                        : "r"(af[mt][0]), "r"(af[mt][1]), "r"(af[mt][2]), "r"(af[mt][3]),
                          "r"(bf[nt][0]), "r"(bf[nt][1]));
                }
        }
    }

    const int g = lane >> 2, t4 = lane & 3;
    #pragma unroll
    for (int mt = 0; mt < 2; mt++) {
        #pragma unroll
        for (int nt = 0; nt < 8; nt++) {
            int r0 = m0 + wm + mt*16 + g;
            int col = n0 + wn + nt*8 + 2*t4;
            if (r0 < M)
                *(__half2*)&C[(size_t)r0 * ldb + col] =
                    __floats2half2_rn(acc[mt][nt][0], acc[mt][nt][1]);
            if (r0 + 8 < M)
                *(__half2*)&C[(size_t)(r0+8) * ldb + col] =
                    __floats2half2_rn(acc[mt][nt][2], acc[mt][nt][3]);
        }
    }
}

// ---------------- phase A: warp per dst node, compute mij -> g_mij[rank] --
__global__ __launch_bounds__(256) void k_edgeA(
    const float* __restrict__ dist, const float* __restrict__ sw)
{
    const int warp = threadIdx.x >> 5;
    const int lane = threadIdx.x & 31;
    const int n = blockIdx.x * 8 + warp;
    if (n >= N_NODES) return;
    const int e0 = g_offD[n], e1 = g_offD[n + 1];
    if (e0 == e1) return;

    // load U[n] row once: lane owns d = lane*4 .. +3, all 16 bases
    float u[16][4];
    const uint2* Up = (const uint2*)(g_Uh + (size_t)n * UW);
    #pragma unroll
    for (int b = 0; b < 16; b++) {
        uint2 q = Up[b * 32 + lane];
        float2 f0 = __half22float2(*(__half2*)&q.x);
        float2 f1 = __half22float2(*(__half2*)&q.y);
        u[b][0] = f0.x; u[b][1] = f0.y; u[b][2] = f1.x; u[b][3] = f1.y;
    }

    const float sigma  = 0.8f / 15.0f;
    const float rsigma = 15.0f / 0.8f;
    const float mu_l   = 0.2f + (float)(lane & 15) * sigma;

    for (int p = e0; p < e1; p++) {
        const int e  = g_eidD[p];
        const int rk = g_rank[e];
        float rinv = 1.0f / dist[e];
        float x = (rinv - mu_l) * rsigma;
        float sv = __expf(-0.5f * x * x) * sw[e];   // lanes 16..31 unused values

        float m0 = 0.f, m1 = 0.f, m2 = 0.f, m3 = 0.f;
        #pragma unroll
        for (int b = 0; b < 16; b++) {
            float sb = __shfl_sync(0xffffffffu, sv, b);
            m0 += sb * u[b][0];
            m1 += sb * u[b][1];
            m2 += sb * u[b][2];
            m3 += sb * u[b][3];
        }
        *(float4*)&g_mij[(size_t)rk * DIM + lane * 4] = make_float4(m0, m1, m2, m3);
    }
}

// ---------------- phase B: warp per src node, reduce + silu -> zi ---------
__global__ __launch_bounds__(256) void k_edgeB() {
    const int warp = threadIdx.x >> 5;
    const int lane = threadIdx.x & 31;
    const int n = blockIdx.x * 8 + warp;
    if (n >= N_NODES) return;

    const size_t base = (size_t)n * DIM + lane * 4;
    float4 a = *(const float4*)&g_zself[base];
    float acc0 = a.x, acc1 = a.y, acc2 = a.z, acc3 = a.w;

    const int p0 = g_offS[n], p1 = g_offS[n + 1];
    for (int p = p0; p < p1; p++) {
        float4 m = *(const float4*)&g_mij[(size_t)p * DIM + lane * 4];
        acc0 += m.x; acc1 += m.y; acc2 += m.z; acc3 += m.w;
    }
    float4 o;
    o.x = silu_f(acc0); o.y = silu_f(acc1);
    o.z = silu_f(acc2); o.w = silu_f(acc3);
    *(float4*)&g_zi[base] = o;
}

// ---------------- host driver ----------------
extern "C" void kernel_launch(void* const* d_in, const int* in_sizes, int n_in,
                              void* d_out, int out_size)
{
    const int*   species = (const int*)  d_in[0];
    const int*   esrc    = (const int*)  d_in[1];
    const int*   edst    = (const int*)  d_in[2];
    const float* dist    = (const float*)d_in[3];
    const float* swp     = (const float*)d_in[4];
    const float* Z       = (const float*)d_in[5];
    const float* Ws0     = (const float*)d_in[6];
    const float* bs0     = (const float*)d_in[7];
    const float* V0      = (const float*)d_in[8];
    const float* Ws1     = (const float*)d_in[9];
    const float* bs1     = (const float*)d_in[10];
    const float* V1      = (const float*)d_in[11];
    const float* Won_a   = (const float*)d_in[12];
    const float* bon_a   = (const float*)d_in[13];
    const float* Won_b   = (const float*)d_in[14];
    const float* bon_b   = (const float*)d_in[15];
    float* out = (float*)d_out;

    float *zi16, *zi, *zself, *h;
    __half *Uh, *Vth, *zih;
    cudaGetSymbolAddress((void**)&zi16,  g_zi16);
    cudaGetSymbolAddress((void**)&zi,    g_zi);
    cudaGetSymbolAddress((void**)&zself, g_zself);
    cudaGetSymbolAddress((void**)&h,     g_h);
    cudaGetSymbolAddress((void**)&Uh,    g_Uh);
    cudaGetSymbolAddress((void**)&Vth,   g_Vth);
    cudaGetSymbolAddress((void**)&zih,   g_zih);

    int *degD, *offD, *curD, *degS, *offS, *curS;
    cudaGetSymbolAddress((void**)&degD, g_degD);
    cudaGetSymbolAddress((void**)&offD, g_offD);
    cudaGetSymbolAddress((void**)&curD, g_curD);
    cudaGetSymbolAddress((void**)&degS, g_degS);
    cudaGetSymbolAddress((void**)&offS, g_offS);
    cudaGetSymbolAddress((void**)&curS, g_curS);

    const int ND = N_NODES * DIM;
    const int MB = (N_NODES + 127) / 128;
    dim3 gemm128(1,  MB);
    dim3 gemmU  (UW / 128, MB);
    const int EB = (N_EDGES + 255) / 256;
    const int NBK = (N_NODES + 7) / 8;

    // ---- graph preprocessing (both CSRs; reused by both layers) ----
    k_zero_deg<<<(N_NODES + 255) / 256, 256>>>();
    k_count2<<<EB, 256>>>(edst, esrc);
    k_scan<<<1, 256>>>(degD, offD, curD);
    k_scan<<<1, 256>>>(degS, offS, curS);
    k_fillD<<<EB, 256>>>(edst);
    k_fillS<<<EB, 256>>>(esrc);

    // ---- layer 0 ----
    k_embed<<<(N_NODES * ZD + 255) / 256, 256>>>(species, Z);
    k_transpose<<<(ZD * UW + 255) / 256, 256>>>(V0, ZD);
    k_f2h<<<(N_NODES * ZD + 255) / 256, 256>>>(zi16, zih, N_NODES * ZD);

    k_gemm2<0><<<gemm128, 256>>>(zi16, Ws0, bs0, nullptr, zself,
                                 N_NODES, ZD, ZD, DIM, DIM, 0);
    k_hgemm<<<gemmU, 256>>>(zih, Vth, Uh, N_NODES, ZD, UW);

    k_edgeA<<<NBK, 256>>>(dist, swp);
    k_edgeB<<<NBK, 256>>>();

    for (int j = 0; j < 3; j++) {
        const float* Wa = Won_a + (size_t)(0 * 3 + j) * DIM * DIM;
        const float* ba = bon_a + (size_t)(0 * 3 + j) * DIM;
        const float* Wb = Won_b + (size_t)(0 * 3 + j) * DIM * DIM;
        const float* bb = bon_b + (size_t)(0 * 3 + j) * DIM;
        k_gemm2<0><<<gemm128, 256>>>(zi, Wa, ba, nullptr, h,
                                     N_NODES, DIM, DIM, DIM, DIM, 1);
        k_gemm2<0><<<gemm128, 256>>>(h, Wb, bb, zi, zi,
                                     N_NODES, DIM, DIM, DIM, DIM, 0);
    }
    k_copy0<<<(ND + 255) / 256, 256>>>(out);

    // ---- layer 1 ----
    k_transpose<<<(DIM * UW + 255) / 256, 256>>>(V1, DIM);
    k_f2h<<<(ND + 255) / 256, 256>>>(zi, zih, ND);

    k_gemm2<0><<<gemm128, 256>>>(zi, Ws1, bs1, nullptr, zself,
                                 N_NODES, DIM, DIM, DIM, DIM, 0);
    k_hgemm<<<gemmU, 256>>>(zih, Vth, Uh, N_NODES, DIM, UW);

    k_edgeA<<<NBK, 256>>>(dist, swp);
    k_edgeB<<<NBK, 256>>>();

    for (int j = 0; j < 3; j++) {
        const float* Wa = Won_a + (size_t)(1 * 3 + j) * DIM * DIM;
        const float* ba = bon_a + (size_t)(1 * 3 + j) * DIM;
        const float* Wb = Won_b + (size_t)(1 * 3 + j) * DIM * DIM;
        const float* bb = bon_b + (size_t)(1 * 3 + j) * DIM;
        k_gemm2<0><<<gemm128, 256>>>(zi, Wa, ba, nullptr, h,
                                     N_NODES, DIM, DIM, DIM, DIM, 1);
        k_gemm2<0><<<gemm128, 256>>>(h, Wb, bb, zi, zi,
                                     N_NODES, DIM, DIM, DIM, DIM, 0);
    }
    k_copy1<<<(ND + 255) / 256, 256>>>(out);
}

// round 5
// speedup vs baseline: 1.4315x; 1.4315x over previous
#include <cuda_runtime.h>
#include <cuda_fp16.h>
#include <math.h>

#define N_NODES 20000
#define N_EDGES 400000
#define DIM 128
#define NB 16
#define ZD 16
#define UW (NB*DIM)   // 2048
#define NLAYERS 2

// ---------------- device scratch (static, no allocations) ----------------
__device__ float  g_zi16[N_NODES*ZD];
__device__ float  g_zi[N_NODES*DIM];
__device__ float  g_zself[N_NODES*DIM];
__device__ __half g_Uh[(size_t)N_NODES*UW];     // U[n][b][d] fp16
__device__ __half g_Vth[DIM*UW];                // V^T fp16 (K x NB*DIM)
__device__ __half g_zih[N_NODES*DIM];           // fp16 copy of activations
__device__ __half g_Wah[NLAYERS*3*DIM*DIM];     // onsite Wa fp16
__device__ __half g_Wbh[NLAYERS*3*DIM*DIM];     // onsite Wb fp16

// CSR scratch (by dst)
__device__ int g_degD[N_NODES], g_offD[N_NODES+1], g_curD[N_NODES], g_eidD[N_EDGES];

__device__ __forceinline__ float silu_f(float x) {
    return x / (1.0f + __expf(-x));
}

// ---------------- small kernels ----------------
__global__ void k_embed(const int* __restrict__ species, const float* __restrict__ Z) {
    int t = blockIdx.x * blockDim.x + threadIdx.x;
    if (t < N_NODES * ZD) {
        int n = t >> 4, k = t & 15;
        g_zi16[t] = Z[species[n] * ZD + k];
    }
}

__global__ void k_transpose(const float* __restrict__ V, int K) {
    int t = blockIdx.x * blockDim.x + threadIdx.x;
    if (t < K * UW) {
        int j = t % UW;
        int k = t / UW;
        int b = j >> 7, d = j & 127;
        g_Vth[t] = __float2half(V[((size_t)b * K + k) * DIM + d]);
    }
}

__global__ void k_f2h(const float* __restrict__ src, __half* __restrict__ dst, int n) {
    int t = blockIdx.x * blockDim.x + threadIdx.x;
    if (t < n) dst[t] = __float2half(src[t]);
}

__global__ void k_wconv(const float* __restrict__ Wa, const float* __restrict__ Wb) {
    int t = blockIdx.x * blockDim.x + threadIdx.x;
    if (t < NLAYERS * 3 * DIM * DIM) {
        g_Wah[t] = __float2half(Wa[t]);
        g_Wbh[t] = __float2half(Wb[t]);
    }
}

__global__ void k_copy0(float* __restrict__ out) {
    int t = blockIdx.x * blockDim.x + threadIdx.x;
    if (t < N_NODES * DIM) {
        int n = t >> 7, d = t & 127;
        out[N_NODES * DIM + n * 2 * DIM + d] = g_zi[t];
    }
}

__global__ void k_copy1(float* __restrict__ out) {
    int t = blockIdx.x * blockDim.x + threadIdx.x;
    if (t < N_NODES * DIM) {
        int n = t >> 7, d = t & 127;
        float v = g_zi[t];
        out[t] = v;
        out[N_NODES * DIM + n * 2 * DIM + DIM + d] = v;
    }
}

// ---------------- CSR build (by dst only) ----------------
__global__ void k_zero_deg() {
    int t = blockIdx.x * blockDim.x + threadIdx.x;
    if (t < N_NODES) g_degD[t] = 0;
}
__global__ void k_count(const int* __restrict__ edst) {
    int e = blockIdx.x * blockDim.x + threadIdx.x;
    if (e < N_EDGES) atomicAdd(&g_degD[edst[e]], 1);
}
// fast single-block scan: 1024 threads, deg staged in dynamic smem
__global__ void k_scan_fast() {
    extern __shared__ int sm_i[];
    int* sdeg = sm_i;                 // N_NODES ints
    int* part = sm_i + N_NODES;       // 1024 ints
    const int t = threadIdx.x;
    for (int i = t; i < N_NODES; i += 1024) sdeg[i] = g_degD[i];
    __syncthreads();

    const int CH = (N_NODES + 1023) / 1024;   // 20
    const int base = t * CH;
    int s = 0;
    #pragma unroll 4
    for (int i = 0; i < CH; i++) {
        int idx = base + i;
        if (idx < N_NODES) s += sdeg[idx];
    }
    part[t] = s;
    __syncthreads();
    #pragma unroll
    for (int d = 1; d < 1024; d <<= 1) {
        int v = (t >= d) ? part[t - d] : 0;
        __syncthreads();
        part[t] += v;
        __syncthreads();
    }
    int run = (t > 0) ? part[t - 1] : 0;
    for (int i = 0; i < CH; i++) {
        int idx = base + i;
        if (idx < N_NODES) {
            g_offD[idx] = run;
            g_curD[idx] = run;
            run += sdeg[idx];
        }
    }
    if (t == 1023) g_offD[N_NODES] = part[1023];
}
__global__ void k_fillD(const int* __restrict__ edst) {
    int e = blockIdx.x * blockDim.x + threadIdx.x;
    if (e < N_EDGES) {
        int pos = atomicAdd(&g_curD[edst[e]], 1);
        g_eidD[pos] = e;
    }
}

// ---------------- fp32 SGEMM (zself), BM=BN=128, 8x8/thread ---------------
__global__ __launch_bounds__(256, 2) void k_gemm2(
    const float* __restrict__ A, const float* __restrict__ B,
    const float* __restrict__ bias, float* __restrict__ C,
    int M, int K, int lda, int ldb, int ldc)
{
    __shared__ float As[16][136];
    __shared__ float Bs[16][128];

    const int t    = threadIdx.x;
    const int warp = t >> 5, lane = t & 31;
    const int wr = warp & 3, wc = warp >> 2;
    const int lr = lane >> 3, lc = lane & 7;
    const int row0 = wr * 32 + lr * 8;
    const int col0 = wc * 64 + lc * 8;
    const int m0 = blockIdx.y * 128, n0 = blockIdx.x * 128;

    const int arow = t >> 1;
    const int ak   = (t & 1) * 8;
    const int brow = t >> 4;
    const int bcol = (t & 15) * 8;

    float acc[8][8];
    #pragma unroll
    for (int i = 0; i < 8; i++)
        #pragma unroll
        for (int j = 0; j < 8; j++) acc[i][j] = 0.0f;

    for (int k0 = 0; k0 < K; k0 += 16) {
        float4 a0 = make_float4(0.f,0.f,0.f,0.f), a1 = a0;
        const int gm = m0 + arow;
        if (gm < M) {
            a0 = *(const float4*)&A[(size_t)gm * lda + k0 + ak];
            a1 = *(const float4*)&A[(size_t)gm * lda + k0 + ak + 4];
        }
        float4 b0 = *(const float4*)&B[(size_t)(k0 + brow) * ldb + n0 + bcol];
        float4 b1 = *(const float4*)&B[(size_t)(k0 + brow) * ldb + n0 + bcol + 4];

        __syncthreads();
        As[ak+0][arow] = a0.x; As[ak+1][arow] = a0.y;
        As[ak+2][arow] = a0.z; As[ak+3][arow] = a0.w;
        As[ak+4][arow] = a1.x; As[ak+5][arow] = a1.y;
        As[ak+6][arow] = a1.z; As[ak+7][arow] = a1.w;
        *(float4*)&Bs[brow][bcol]     = b0;
        *(float4*)&Bs[brow][bcol + 4] = b1;
        __syncthreads();

        #pragma unroll
        for (int kk = 0; kk < 16; kk++) {
            float4 x0 = *(float4*)&As[kk][row0];
            float4 x1 = *(float4*)&As[kk][row0 + 4];
            float4 y0 = *(float4*)&Bs[kk][col0];
            float4 y1 = *(float4*)&Bs[kk][col0 + 4];
            float ar[8] = {x0.x,x0.y,x0.z,x0.w,x1.x,x1.y,x1.z,x1.w};
            float br[8] = {y0.x,y0.y,y0.z,y0.w,y1.x,y1.y,y1.z,y1.w};
            #pragma unroll
            for (int i = 0; i < 8; i++)
                #pragma unroll
                for (int j = 0; j < 8; j++)
                    acc[i][j] += ar[i] * br[j];
        }
    }

    #pragma unroll
    for (int i = 0; i < 8; i++) {
        int m = m0 + row0 + i;
        if (m >= M) continue;
        float v[8];
        #pragma unroll
        for (int j = 0; j < 8; j++) v[j] = acc[i][j] + bias[n0 + col0 + j];
        float* cp = &C[(size_t)m * ldc + n0 + col0];
        ((float4*)cp)[0] = make_float4(v[0], v[1], v[2], v[3]);
        ((float4*)cp)[1] = make_float4(v[4], v[5], v[6], v[7]);
    }
}

// ---------------- shared mma helper: 32x64 warp tile over K=128 in smem ---
__device__ __forceinline__ void mma_k128(
    const __half (*Amat)[136], const __half (*Bmat)[136],
    int wm, int wn, int lane, float acc[2][8][4])
{
    #pragma unroll
    for (int kc = 0; kc < 128; kc += 16) {
        unsigned af[2][4];
        #pragma unroll
        for (int mt = 0; mt < 2; mt++) {
            const __half* p = &Amat[wm + mt*16 + (lane & 15)][kc + ((lane >> 4) << 3)];
            unsigned addr = (unsigned)__cvta_generic_to_shared(p);
            asm volatile("ldmatrix.sync.aligned.m8n8.x4.shared.b16 {%0,%1,%2,%3}, [%4];"
                : "=r"(af[mt][0]), "=r"(af[mt][1]), "=r"(af[mt][2]), "=r"(af[mt][3])
                : "r"(addr));
        }
        unsigned bf[8][2];
        #pragma unroll
        for (int q = 0; q < 4; q++) {
            const __half* p = &Bmat[kc + (lane & 15)][wn + q*16 + ((lane >> 4) << 3)];
            unsigned addr = (unsigned)__cvta_generic_to_shared(p);
            asm volatile("ldmatrix.sync.aligned.m8n8.x4.trans.shared.b16 {%0,%1,%2,%3}, [%4];"
                : "=r"(bf[q*2][0]), "=r"(bf[q*2][1]), "=r"(bf[q*2+1][0]), "=r"(bf[q*2+1][1])
                : "r"(addr));
        }
        #pragma unroll
        for (int mt = 0; mt < 2; mt++)
            #pragma unroll
            for (int nt = 0; nt < 8; nt++) {
                asm volatile(
                    "mma.sync.aligned.m16n8k16.row.col.f32.f16.f16.f32 "
                    "{%0,%1,%2,%3}, {%4,%5,%6,%7}, {%8,%9}, {%0,%1,%2,%3};"
                    : "+f"(acc[mt][nt][0]), "+f"(acc[mt][nt][1]),
                      "+f"(acc[mt][nt][2]), "+f"(acc[mt][nt][3])
                    : "r"(af[mt][0]), "r"(af[mt][1]), "r"(af[mt][2]), "r"(af[mt][3]),
                      "r"(bf[nt][0]), "r"(bf[nt][1]));
            }
    }
}

// ---------------- fused onsite block: zi = A + silu(A@Wa+ba)@Wb + bb ------
// A = in (silu applied on load and in residual if PRESILU). 128-row tiles.
template<int PRESILU>
__global__ __launch_bounds__(256) void k_onsite(
    const float* __restrict__ in, const __half* __restrict__ Wa,
    const float* __restrict__ ba, const __half* __restrict__ Wb,
    const float* __restrict__ bb, float* __restrict__ outz)
{
    extern __shared__ __half sm_h[];
    __half (*As)[136] = (__half(*)[136])sm_h;
    __half (*Ws)[136] = (__half(*)[136])(sm_h + 128*136);
    __half (*Hs)[136] = (__half(*)[136])(sm_h + 2*128*136);

    const int t = threadIdx.x;
    const int warp = t >> 5, lane = t & 31;
    const int wm = (warp & 3) * 32, wn = (warp >> 2) * 64;
    const int m0 = blockIdx.x * 128;
    const int r = t >> 1, c0 = (t & 1) * 64;
    const int gm = m0 + r;

    // stage A (+silu) and Wa into smem
    #pragma unroll
    for (int i = 0; i < 16; i++) {
        float4 v = make_float4(0.f,0.f,0.f,0.f);
        if (gm < N_NODES) v = *(const float4*)&in[(size_t)gm * DIM + c0 + i*4];
        if (PRESILU) { v.x=silu_f(v.x); v.y=silu_f(v.y); v.z=silu_f(v.z); v.w=silu_f(v.w); }
        *(__half2*)&As[r][c0 + i*4]     = __floats2half2_rn(v.x, v.y);
        *(__half2*)&As[r][c0 + i*4 + 2] = __floats2half2_rn(v.z, v.w);
    }
    #pragma unroll
    for (int i = 0; i < 8; i++)
        *(uint4*)&Ws[r][c0 + i*8] = *(const uint4*)&Wa[r * DIM + c0 + i*8];
    __syncthreads();

    float acc[2][8][4];
    #pragma unroll
    for (int mt = 0; mt < 2; mt++)
        #pragma unroll
        for (int nt = 0; nt < 8; nt++)
            #pragma unroll
            for (int i = 0; i < 4; i++) acc[mt][nt][i] = 0.0f;

    mma_k128(As, Ws, wm, wn, lane, acc);

    // epilogue 1: h = silu(acc + ba) -> Hs (fp16)
    const int g4 = lane >> 2, t4 = lane & 3;
    #pragma unroll
    for (int mt = 0; mt < 2; mt++) {
        #pragma unroll
        for (int nt = 0; nt < 8; nt++) {
            int col = wn + nt*8 + 2*t4;
            float b0 = ba[col], b1 = ba[col + 1];
            int r0 = wm + mt*16 + g4;
            *(__half2*)&Hs[r0][col] =
                __floats2half2_rn(silu_f(acc[mt][nt][0] + b0), silu_f(acc[mt][nt][1] + b1));
            *(__half2*)&Hs[r0 + 8][col] =
                __floats2half2_rn(silu_f(acc[mt][nt][2] + b0), silu_f(acc[mt][nt][3] + b1));
        }
    }
    __syncthreads();
    // load Wb over Ws
    #pragma unroll
    for (int i = 0; i < 8; i++)
        *(uint4*)&Ws[r][c0 + i*8] = *(const uint4*)&Wb[r * DIM + c0 + i*8];
    __syncthreads();

    #pragma unroll
    for (int mt = 0; mt < 2; mt++)
        #pragma unroll
        for (int nt = 0; nt < 8; nt++)
            #pragma unroll
            for (int i = 0; i < 4; i++) acc[mt][nt][i] = 0.0f;

    mma_k128(Hs, Ws, wm, wn, lane, acc);

    // epilogue 2: out = acc + bb + residual(A)
    #pragma unroll
    for (int mt = 0; mt < 2; mt++) {
        #pragma unroll
        for (int nt = 0; nt < 8; nt++) {
            int col = wn + nt*8 + 2*t4;
            float b0 = bb[col], b1 = bb[col + 1];
            #pragma unroll
            for (int half = 0; half < 2; half++) {
                int row = m0 + wm + mt*16 + g4 + half*8;
                if (row >= N_NODES) continue;
                float2 rv = *(const float2*)&in[(size_t)row * DIM + col];
                if (PRESILU) { rv.x = silu_f(rv.x); rv.y = silu_f(rv.y); }
                float2 o;
                o.x = acc[mt][nt][half*2 + 0] + b0 + rv.x;
                o.y = acc[mt][nt][half*2 + 1] + b1 + rv.y;
                *(float2*)&outz[(size_t)row * DIM + col] = o;
            }
        }
    }
}

// ---------------- fp16 tensor-core GEMM (U-GEMM): C_h = A_h @ B_h ---------
__global__ __launch_bounds__(256, 2) void k_hgemm(
    const __half* __restrict__ A, const __half* __restrict__ B,
    __half* __restrict__ C, int M, int K, int ldb)
{
    __shared__ __half As[128][40];
    __shared__ __half Bs[32][136];

    const int t    = threadIdx.x;
    const int warp = t >> 5, lane = t & 31;
    const int wm = (warp & 3) * 32;
    const int wn = (warp >> 2) * 64;
    const int m0 = blockIdx.y * 128, n0 = blockIdx.x * 128;

    const int arow = t >> 1, ak = (t & 1) * 8;
    const int brow = t >> 4, bcol = (t & 15) * 8;

    float acc[2][8][4];
    #pragma unroll
    for (int mt = 0; mt < 2; mt++)
        #pragma unroll
        for (int nt = 0; nt < 8; nt++)
            #pragma unroll
            for (int i = 0; i < 4; i++) acc[mt][nt][i] = 0.0f;

    const uint4 z4 = make_uint4(0,0,0,0);

    for (int k0 = 0; k0 < K; k0 += 32) {
        const int nsub = (K - k0 >= 32) ? 2 : 1;
        uint4 av0 = z4, av1 = z4, bv0, bv1;
        const int gm = m0 + arow;
        if (gm < M) {
            av0 = *(const uint4*)&A[(size_t)gm * K + k0 + ak];
            if (nsub == 2) av1 = *(const uint4*)&A[(size_t)gm * K + k0 + 16 + ak];
        }
        bv0 = *(const uint4*)&B[(size_t)(k0 + brow) * ldb + n0 + bcol];
        if (nsub == 2) bv1 = *(const uint4*)&B[(size_t)(k0 + 16 + brow) * ldb + n0 + bcol];

        __syncthreads();
        *(uint4*)&As[arow][ak] = av0;
        if (nsub == 2) *(uint4*)&As[arow][16 + ak] = av1;
        *(uint4*)&Bs[brow][bcol] = bv0;
        if (nsub == 2) *(uint4*)&Bs[16 + brow][bcol] = bv1;
        __syncthreads();

        #pragma unroll
        for (int sub = 0; sub < 2; sub++) {
            if (sub >= nsub) break;
            const int kc = sub * 16;

            unsigned af[2][4];
            #pragma unroll
            for (int mt = 0; mt < 2; mt++) {
                const __half* p = &As[wm + mt*16 + (lane & 15)][kc + ((lane >> 4) << 3)];
                unsigned addr = (unsigned)__cvta_generic_to_shared(p);
                asm volatile("ldmatrix.sync.aligned.m8n8.x4.shared.b16 {%0,%1,%2,%3}, [%4];"
                    : "=r"(af[mt][0]), "=r"(af[mt][1]), "=r"(af[mt][2]), "=r"(af[mt][3])
                    : "r"(addr));
            }
            unsigned bf[8][2];
            #pragma unroll
            for (int q = 0; q < 4; q++) {
                const __half* p = &Bs[kc + (lane & 15)][wn + q*16 + ((lane >> 4) << 3)];
                unsigned addr = (unsigned)__cvta_generic_to_shared(p);
                asm volatile("ldmatrix.sync.aligned.m8n8.x4.trans.shared.b16 {%0,%1,%2,%3}, [%4];"
                    : "=r"(bf[q*2][0]), "=r"(bf[q*2][1]), "=r"(bf[q*2+1][0]), "=r"(bf[q*2+1][1])
                    : "r"(addr));
            }
            #pragma unroll
            for (int mt = 0; mt < 2; mt++)
                #pragma unroll
                for (int nt = 0; nt < 8; nt++) {
                    asm volatile(
                        "mma.sync.aligned.m16n8k16.row.col.f32.f16.f16.f32 "
                        "{%0,%1,%2,%3}, {%4,%5,%6,%7}, {%8,%9}, {%0,%1,%2,%3};"
                        : "+f"(acc[mt][nt][0]), "+f"(acc[mt][nt][1]),
                          "+f"(acc[mt][nt][2]), "+f"(acc[mt][nt][3])
                        : "r"(af[mt][0]), "r"(af[mt][1]), "r"(af[mt][2]), "r"(af[mt][3]),
                          "r"(bf[nt][0]), "r"(bf[nt][1]));
                }
        }
    }

    const int g = lane >> 2, t4 = lane & 3;
    #pragma unroll
    for (int mt = 0; mt < 2; mt++) {
        #pragma unroll
        for (int nt = 0; nt < 8; nt++) {
            int r0 = m0 + wm + mt*16 + g;
            int col = n0 + wn + nt*8 + 2*t4;
            if (r0 < M)
                *(__half2*)&C[(size_t)r0 * ldb + col] =
                    __floats2half2_rn(acc[mt][nt][0], acc[mt][nt][1]);
            if (r0 + 8 < M)
                *(__half2*)&C[(size_t)(r0+8) * ldb + col] =
                    __floats2half2_rn(acc[mt][nt][2], acc[mt][nt][3]);
        }
    }
}

// ---------------- edge kernel: warp per dst node, gather + atomic scatter -
__global__ __launch_bounds__(256) void k_edge_csr(
    const int* __restrict__ esrc,
    const float* __restrict__ dist, const float* __restrict__ sw)
{
    const int warp = threadIdx.x >> 5;
    const int lane = threadIdx.x & 31;
    const int n = blockIdx.x * 8 + warp;
    if (n >= N_NODES) return;
    const int e0 = g_offD[n], e1 = g_offD[n + 1];
    if (e0 == e1) return;

    // load U[n] row once: lane owns d = lane*4 .. +3, all 16 bases
    float u[16][4];
    const uint2* Up = (const uint2*)(g_Uh + (size_t)n * UW);
    #pragma unroll
    for (int b = 0; b < 16; b++) {
        uint2 q = Up[b * 32 + lane];
        float2 f0 = __half22float2(*(__half2*)&q.x);
        float2 f1 = __half22float2(*(__half2*)&q.y);
        u[b][0] = f0.x; u[b][1] = f0.y; u[b][2] = f1.x; u[b][3] = f1.y;
    }

    const float sigma  = 0.8f / 15.0f;
    const float rsigma = 15.0f / 0.8f;
    const float mu_l   = 0.2f + (float)(lane & 15) * sigma;

    for (int p = e0; p < e1; p++) {
        const int e   = g_eidD[p];
        const int src = esrc[e];
        float rinv = 1.0f / dist[e];
        float x = (rinv - mu_l) * rsigma;
        float sv = __expf(-0.5f * x * x) * sw[e];

        float m0 = 0.f, m1 = 0.f, m2 = 0.f, m3 = 0.f;
        #pragma unroll
        for (int b = 0; b < 16; b++) {
            float sb = __shfl_sync(0xffffffffu, sv, b);
            m0 += sb * u[b][0];
            m1 += sb * u[b][1];
            m2 += sb * u[b][2];
            m3 += sb * u[b][3];
        }
        float* zp = &g_zself[(size_t)src * DIM + lane * 4];
        asm volatile("red.global.add.v4.f32 [%0], {%1,%2,%3,%4};"
                     :: "l"(zp), "f"(m0), "f"(m1), "f"(m2), "f"(m3) : "memory");
    }
}

// ---------------- host driver ----------------
extern "C" void kernel_launch(void* const* d_in, const int* in_sizes, int n_in,
                              void* d_out, int out_size)
{
    const int*   species = (const int*)  d_in[0];
    const int*   esrc    = (const int*)  d_in[1];
    const int*   edst    = (const int*)  d_in[2];
    const float* dist    = (const float*)d_in[3];
    const float* swp     = (const float*)d_in[4];
    const float* Z       = (const float*)d_in[5];
    const float* Ws0     = (const float*)d_in[6];
    const float* bs0     = (const float*)d_in[7];
    const float* V0      = (const float*)d_in[8];
    const float* Ws1     = (const float*)d_in[9];
    const float* bs1     = (const float*)d_in[10];
    const float* V1      = (const float*)d_in[11];
    const float* Won_a   = (const float*)d_in[12];
    const float* bon_a   = (const float*)d_in[13];
    const float* Won_b   = (const float*)d_in[14];
    const float* bon_b   = (const float*)d_in[15];
    float* out = (float*)d_out;

    float *zi16, *zi, *zself;
    __half *Uh, *Vth, *zih, *Wah, *Wbh;
    cudaGetSymbolAddress((void**)&zi16,  g_zi16);
    cudaGetSymbolAddress((void**)&zi,    g_zi);
    cudaGetSymbolAddress((void**)&zself, g_zself);
    cudaGetSymbolAddress((void**)&Uh,    g_Uh);
    cudaGetSymbolAddress((void**)&Vth,   g_Vth);
    cudaGetSymbolAddress((void**)&zih,   g_zih);
    cudaGetSymbolAddress((void**)&Wah,   g_Wah);
    cudaGetSymbolAddress((void**)&Wbh,   g_Wbh);

    const int ND = N_NODES * DIM;
    const int MB = (N_NODES + 127) / 128;       // 157
    dim3 gemm128(1,  MB);
    dim3 gemmU  (UW / 128, MB);
    const int EB = (N_EDGES + 255) / 256;
    const int NBK = (N_NODES + 7) / 8;

    // dynamic smem limits
    const int SCAN_SMEM   = (N_NODES + 1024) * (int)sizeof(int);     // ~84 KB
    const int ONSITE_SMEM = 3 * 128 * 136 * (int)sizeof(__half);     // ~104 KB
    static int attr_done = 0;
    if (!attr_done) {
        cudaFuncSetAttribute(k_scan_fast, cudaFuncAttributeMaxDynamicSharedMemorySize, SCAN_SMEM);
        cudaFuncSetAttribute(k_onsite<0>, cudaFuncAttributeMaxDynamicSharedMemorySize, ONSITE_SMEM);
        cudaFuncSetAttribute(k_onsite<1>, cudaFuncAttributeMaxDynamicSharedMemorySize, ONSITE_SMEM);
        attr_done = 1;
    }

    // ---- shared preprocessing ----
    k_embed<<<(N_NODES * ZD + 255) / 256, 256>>>(species, Z);
    k_transpose<<<(ZD * UW + 255) / 256, 256>>>(V0, ZD);
    k_f2h<<<(N_NODES * ZD + 255) / 256, 256>>>(zi16, zih, N_NODES * ZD);
    k_zero_deg<<<(N_NODES + 255) / 256, 256>>>();
    k_count<<<EB, 256>>>(edst);
    k_scan_fast<<<1, 1024, SCAN_SMEM>>>();
    k_fillD<<<EB, 256>>>(edst);
    k_wconv<<<(NLAYERS * 3 * DIM * DIM + 255) / 256, 256>>>(Won_a, Won_b);

    // ---- layer 0 ----
    k_gemm2<<<gemm128, 256>>>(zi16, Ws0, bs0, zself, N_NODES, ZD, ZD, DIM, DIM);
    k_hgemm<<<gemmU, 256>>>(zih, Vth, Uh, N_NODES, ZD, UW);
    k_edge_csr<<<NBK, 256>>>(esrc, dist, swp);

    // onsite: j=0 consumes zself with silu-on-load; j=1,2 consume zi
    k_onsite<1><<<MB, 256, ONSITE_SMEM>>>(zself,
        Wah + 0*DIM*DIM, bon_a + 0*DIM, Wbh + 0*DIM*DIM, bon_b + 0*DIM, zi);
    k_onsite<0><<<MB, 256, ONSITE_SMEM>>>(zi,
        Wah + 1*DIM*DIM, bon_a + 1*DIM, Wbh + 1*DIM*DIM, bon_b + 1*DIM, zi);
    k_onsite<0><<<MB, 256, ONSITE_SMEM>>>(zi,
        Wah + 2*DIM*DIM, bon_a + 2*DIM, Wbh + 2*DIM*DIM, bon_b + 2*DIM, zi);
    k_copy0<<<(ND + 255) / 256, 256>>>(out);

    // ---- layer 1 ----
    k_transpose<<<(DIM * UW + 255) / 256, 256>>>(V1, DIM);
    k_f2h<<<(ND + 255) / 256, 256>>>(zi, zih, ND);

    k_gemm2<<<gemm128, 256>>>(zi, Ws1, bs1, zself, N_NODES, DIM, DIM, DIM, DIM);
    k_hgemm<<<gemmU, 256>>>(zih, Vth, Uh, N_NODES, DIM, UW);
    k_edge_csr<<<NBK, 256>>>(esrc, dist, swp);

    k_onsite<1><<<MB, 256, ONSITE_SMEM>>>(zself,
        Wah + 3*DIM*DIM, bon_a + 3*DIM, Wbh + 3*DIM*DIM, bon_b + 3*DIM, zi);
    k_onsite<0><<<MB, 256, ONSITE_SMEM>>>(zi,
        Wah + 4*DIM*DIM, bon_a + 4*DIM, Wbh + 4*DIM*DIM, bon_b + 4*DIM, zi);
    k_onsite<0><<<MB, 256, ONSITE_SMEM>>>(zi,
        Wah + 5*DIM*DIM, bon_a + 5*DIM, Wbh + 5*DIM*DIM, bon_b + 5*DIM, zi);
    k_copy1<<<(ND + 255) / 256, 256>>>(out);
}

// round 6
// speedup vs baseline: 1.7658x; 1.2335x over previous
#include <cuda_runtime.h>
#include <cuda_fp16.h>
#include <math.h>

#define N_NODES 20000
#define N_EDGES 400000
#define DIM 128
#define NB 16
#define ZD 16
#define NLAYERS 2
#define KT1 (NB*DIM)   // 2048
#define KT0 (NB*ZD)    // 256

// ---------------- device scratch (static, no allocations) ----------------
__device__ float  g_zi16[N_NODES*ZD];
__device__ float  g_zi[N_NODES*DIM];
__device__ float  g_zself[N_NODES*DIM];
__device__ __half g_A[(size_t)N_NODES*KT1];     // aggregated T rows (fp16)
__device__ __half g_Vh0[KT0*DIM];               // V0.reshape(-1,128) fp16
__device__ __half g_Vh1[KT1*DIM];               // V1.reshape(-1,128) fp16
__device__ __half g_Wah[NLAYERS*3*DIM*DIM];     // onsite Wa fp16
__device__ __half g_Wbh[NLAYERS*3*DIM*DIM];     // onsite Wb fp16

// CSR by src + reordered edge data
__device__ int   g_degS[N_NODES], g_offS[N_NODES+1], g_curS[N_NODES];
__device__ int   g_dstS[N_EDGES];
__device__ float g_distS[N_EDGES];
__device__ float g_swS[N_EDGES];

__device__ __forceinline__ float silu_f(float x) {
    return x / (1.0f + __expf(-x));
}

// ---------------- small kernels ----------------
__global__ void k_embed(const int* __restrict__ species, const float* __restrict__ Z) {
    int t = blockIdx.x * blockDim.x + threadIdx.x;
    if (t < N_NODES * ZD) {
        int n = t >> 4, k = t & 15;
        g_zi16[t] = Z[species[n] * ZD + k];
    }
}

__global__ void k_f2h(const float* __restrict__ src, __half* __restrict__ dst, int n) {
    int t = blockIdx.x * blockDim.x + threadIdx.x;
    if (t < n) dst[t] = __float2half(src[t]);
}

__global__ void k_wconv(const float* __restrict__ Wa, const float* __restrict__ Wb) {
    int t = blockIdx.x * blockDim.x + threadIdx.x;
    if (t < NLAYERS * 3 * DIM * DIM) {
        g_Wah[t] = __float2half(Wa[t]);
        g_Wbh[t] = __float2half(Wb[t]);
    }
}

// ---------------- CSR build (by src) ----------------
__global__ void k_zero_deg() {
    int t = blockIdx.x * blockDim.x + threadIdx.x;
    if (t < N_NODES) g_degS[t] = 0;
}
__global__ void k_count(const int* __restrict__ esrc) {
    int e = blockIdx.x * blockDim.x + threadIdx.x;
    if (e < N_EDGES) atomicAdd(&g_degS[esrc[e]], 1);
}
__global__ void k_scan_fast() {
    extern __shared__ int sm_i[];
    int* sdeg = sm_i;
    int* part = sm_i + N_NODES;
    const int t = threadIdx.x;
    for (int i = t; i < N_NODES; i += 1024) sdeg[i] = g_degS[i];
    __syncthreads();

    const int CH = (N_NODES + 1023) / 1024;   // 20
    const int base = t * CH;
    int s = 0;
    #pragma unroll 4
    for (int i = 0; i < CH; i++) {
        int idx = base + i;
        if (idx < N_NODES) s += sdeg[idx];
    }
    part[t] = s;
    __syncthreads();
    #pragma unroll
    for (int d = 1; d < 1024; d <<= 1) {
        int v = (t >= d) ? part[t - d] : 0;
        __syncthreads();
        part[t] += v;
        __syncthreads();
    }
    int run = (t > 0) ? part[t - 1] : 0;
    for (int i = 0; i < CH; i++) {
        int idx = base + i;
        if (idx < N_NODES) {
            g_offS[idx] = run;
            g_curS[idx] = run;
            run += sdeg[idx];
        }
    }
    if (t == 1023) g_offS[N_NODES] = part[1023];
}
__global__ void k_fillS(const int* __restrict__ esrc, const int* __restrict__ edst,
                        const float* __restrict__ dist, const float* __restrict__ sw) {
    int e = blockIdx.x * blockDim.x + threadIdx.x;
    if (e < N_EDGES) {
        int pos = atomicAdd(&g_curS[esrc[e]], 1);
        g_dstS[pos]  = edst[e];
        g_distS[pos] = dist[e];
        g_swS[pos]   = sw[e];
    }
}

// ---------------- fp32 SGEMM (zself): BM=BN=128, 8x8/thread ---------------
__global__ __launch_bounds__(256, 2) void k_gemm2(
    const float* __restrict__ A, const float* __restrict__ B,
    const float* __restrict__ bias, float* __restrict__ C,
    int M, int K, int lda, int ldb, int ldc)
{
    __shared__ float As[16][136];
    __shared__ float Bs[16][128];

    const int t    = threadIdx.x;
    const int warp = t >> 5, lane = t & 31;
    const int wr = warp & 3, wc = warp >> 2;
    const int lr = lane >> 3, lc = lane & 7;
    const int row0 = wr * 32 + lr * 8;
    const int col0 = wc * 64 + lc * 8;
    const int m0 = blockIdx.y * 128, n0 = blockIdx.x * 128;

    const int arow = t >> 1;
    const int ak   = (t & 1) * 8;
    const int brow = t >> 4;
    const int bcol = (t & 15) * 8;

    float acc[8][8];
    #pragma unroll
    for (int i = 0; i < 8; i++)
        #pragma unroll
        for (int j = 0; j < 8; j++) acc[i][j] = 0.0f;

    for (int k0 = 0; k0 < K; k0 += 16) {
        float4 a0 = make_float4(0.f,0.f,0.f,0.f), a1 = a0;
        const int gm = m0 + arow;
        if (gm < M) {
            a0 = *(const float4*)&A[(size_t)gm * lda + k0 + ak];
            a1 = *(const float4*)&A[(size_t)gm * lda + k0 + ak + 4];
        }
        float4 b0 = *(const float4*)&B[(size_t)(k0 + brow) * ldb + n0 + bcol];
        float4 b1 = *(const float4*)&B[(size_t)(k0 + brow) * ldb + n0 + bcol + 4];

        __syncthreads();
        As[ak+0][arow] = a0.x; As[ak+1][arow] = a0.y;
        As[ak+2][arow] = a0.z; As[ak+3][arow] = a0.w;
        As[ak+4][arow] = a1.x; As[ak+5][arow] = a1.y;
        As[ak+6][arow] = a1.z; As[ak+7][arow] = a1.w;
        *(float4*)&Bs[brow][bcol]     = b0;
        *(float4*)&Bs[brow][bcol + 4] = b1;
        __syncthreads();

        #pragma unroll
        for (int kk = 0; kk < 16; kk++) {
            float4 x0 = *(float4*)&As[kk][row0];
            float4 x1 = *(float4*)&As[kk][row0 + 4];
            float4 y0 = *(float4*)&Bs[kk][col0];
            float4 y1 = *(float4*)&Bs[kk][col0 + 4];
            float ar[8] = {x0.x,x0.y,x0.z,x0.w,x1.x,x1.y,x1.z,x1.w};
            float br[8] = {y0.x,y0.y,y0.z,y0.w,y1.x,y1.y,y1.z,y1.w};
            #pragma unroll
            for (int i = 0; i < 8; i++)
                #pragma unroll
                for (int j = 0; j < 8; j++)
                    acc[i][j] += ar[i] * br[j];
        }
    }

    #pragma unroll
    for (int i = 0; i < 8; i++) {
        int m = m0 + row0 + i;
        if (m >= M) continue;
        float v[8];
        #pragma unroll
        for (int j = 0; j < 8; j++) v[j] = acc[i][j] + bias[n0 + col0 + j];
        float* cp = &C[(size_t)m * ldc + n0 + col0];
        ((float4*)cp)[0] = make_float4(v[0], v[1], v[2], v[3]);
        ((float4*)cp)[1] = make_float4(v[4], v[5], v[6], v[7]);
    }
}

// ---------------- edge aggregation: T[n] = sum_{e:src=n} s_e x z_dst ------
// layer 1: z = g_zi (DIM=128). Warp per node; 64 f32 accumulators per lane.
__global__ __launch_bounds__(256) void k_edgeT1() {
    const int warp = threadIdx.x >> 5;
    const int lane = threadIdx.x & 31;
    const int n = blockIdx.x * 8 + warp;
    if (n >= N_NODES) return;

    float acc[16][4];
    #pragma unroll
    for (int b = 0; b < 16; b++)
        #pragma unroll
        for (int i = 0; i < 4; i++) acc[b][i] = 0.0f;

    const int p0 = g_offS[n], p1 = g_offS[n + 1];
    const float sigma  = 0.8f / 15.0f;
    const float rsigma = 15.0f / 0.8f;
    const float mu_l   = 0.2f + (float)(lane & 15) * sigma;

    for (int p = p0; p < p1; p++) {
        const int dst = g_dstS[p];
        const float di = g_distS[p];
        const float sw = g_swS[p];
        float rinv = 1.0f / di;
        float x = (rinv - mu_l) * rsigma;
        float sv = __expf(-0.5f * x * x) * sw;

        float4 zv = *(const float4*)&g_zi[(size_t)dst * DIM + lane * 4];
        #pragma unroll
        for (int b = 0; b < 16; b++) {
            float sb = __shfl_sync(0xffffffffu, sv, b);
            acc[b][0] += sb * zv.x;
            acc[b][1] += sb * zv.y;
            acc[b][2] += sb * zv.z;
            acc[b][3] += sb * zv.w;
        }
    }

    __half* Ap = g_A + (size_t)n * KT1;
    #pragma unroll
    for (int b = 0; b < 16; b++) {
        __half2 h0 = __floats2half2_rn(acc[b][0], acc[b][1]);
        __half2 h1 = __floats2half2_rn(acc[b][2], acc[b][3]);
        uint2 st;
        st.x = *(unsigned*)&h0;
        st.y = *(unsigned*)&h1;
        *(uint2*)&Ap[b * DIM + lane * 4] = st;
    }
}

// layer 0: z = g_zi16 (ZD=16). Lane owns k=lane&15, b in [(lane>>4)*8, +8).
__global__ __launch_bounds__(256) void k_edgeT0() {
    const int warp = threadIdx.x >> 5;
    const int lane = threadIdx.x & 31;
    const int n = blockIdx.x * 8 + warp;
    if (n >= N_NODES) return;

    float acc[8];
    #pragma unroll
    for (int j = 0; j < 8; j++) acc[j] = 0.0f;

    const int p0 = g_offS[n], p1 = g_offS[n + 1];
    const int k  = lane & 15;
    const int bb = (lane >> 4) * 8;
    const float sigma  = 0.8f / 15.0f;
    const float rsigma = 15.0f / 0.8f;
    const float mu_l   = 0.2f + (float)k * sigma;

    for (int p = p0; p < p1; p++) {
        const int dst = g_dstS[p];
        const float di = g_distS[p];
        const float sw = g_swS[p];
        float rinv = 1.0f / di;
        float x = (rinv - mu_l) * rsigma;
        float sv = __expf(-0.5f * x * x) * sw;   // basis index = k

        float zv = g_zi16[dst * ZD + k];
        #pragma unroll
        for (int j = 0; j < 8; j++) {
            float sb = __shfl_sync(0xffffffffu, sv, bb + j);
            acc[j] += sb * zv;
        }
    }

    __half* Ap = g_A + (size_t)n * KT0;
    #pragma unroll
    for (int j = 0; j < 8; j++)
        Ap[(bb + j) * ZD + k] = __float2half(acc[j]);
}

// ---------------- TC GEMM + epilogue: zi = silu(T @ Vflat + zself) --------
// M=20000, N=128 (gridX=1), K in {256, 2048}. A fp16 [M x K], B fp16 [K x 128].
__global__ __launch_bounds__(256, 2) void k_hgemmE(
    const __half* __restrict__ A, const __half* __restrict__ B,
    const float* __restrict__ zself, float* __restrict__ outz, int K)
{
    __shared__ __half As[128][40];
    __shared__ __half Bs[32][136];

    const int t    = threadIdx.x;
    const int warp = t >> 5, lane = t & 31;
    const int wm = (warp & 3) * 32;
    const int wn = (warp >> 2) * 64;
    const int m0 = blockIdx.x * 128;

    const int arow = t >> 1, ak = (t & 1) * 8;
    const int brow = t >> 4, bcol = (t & 15) * 8;

    float acc[2][8][4];
    #pragma unroll
    for (int mt = 0; mt < 2; mt++)
        #pragma unroll
        for (int nt = 0; nt < 8; nt++)
            #pragma unroll
            for (int i = 0; i < 4; i++) acc[mt][nt][i] = 0.0f;

    const uint4 z4 = make_uint4(0,0,0,0);

    for (int k0 = 0; k0 < K; k0 += 32) {
        uint4 av0 = z4, av1 = z4;
        const int gm = m0 + arow;
        if (gm < N_NODES) {
            av0 = *(const uint4*)&A[(size_t)gm * K + k0 + ak];
            av1 = *(const uint4*)&A[(size_t)gm * K + k0 + 16 + ak];
        }
        uint4 bv0 = *(const uint4*)&B[(size_t)(k0 + brow) * DIM + bcol];
        uint4 bv1 = *(const uint4*)&B[(size_t)(k0 + 16 + brow) * DIM + bcol];

        __syncthreads();
        *(uint4*)&As[arow][ak]      = av0;
        *(uint4*)&As[arow][16 + ak] = av1;
        *(uint4*)&Bs[brow][bcol]      = bv0;
        *(uint4*)&Bs[16 + brow][bcol] = bv1;
        __syncthreads();

        #pragma unroll
        for (int sub = 0; sub < 2; sub++) {
            const int kc = sub * 16;
            unsigned af[2][4];
            #pragma unroll
            for (int mt = 0; mt < 2; mt++) {
                const __half* p = &As[wm + mt*16 + (lane & 15)][kc + ((lane >> 4) << 3)];
                unsigned addr = (unsigned)__cvta_generic_to_shared(p);
                asm volatile("ldmatrix.sync.aligned.m8n8.x4.shared.b16 {%0,%1,%2,%3}, [%4];"
                    : "=r"(af[mt][0]), "=r"(af[mt][1]), "=r"(af[mt][2]), "=r"(af[mt][3])
                    : "r"(addr));
            }
            unsigned bf[8][2];
            #pragma unroll
            for (int q = 0; q < 4; q++) {
                const __half* p = &Bs[kc + (lane & 15)][wn + q*16 + ((lane >> 4) << 3)];
                unsigned addr = (unsigned)__cvta_generic_to_shared(p);
                asm volatile("ldmatrix.sync.aligned.m8n8.x4.trans.shared.b16 {%0,%1,%2,%3}, [%4];"
                    : "=r"(bf[q*2][0]), "=r"(bf[q*2][1]), "=r"(bf[q*2+1][0]), "=r"(bf[q*2+1][1])
                    : "r"(addr));
            }
            #pragma unroll
            for (int mt = 0; mt < 2; mt++)
                #pragma unroll
                for (int nt = 0; nt < 8; nt++) {
                    asm volatile(
                        "mma.sync.aligned.m16n8k16.row.col.f32.f16.f16.f32 "
                        "{%0,%1,%2,%3}, {%4,%5,%6,%7}, {%8,%9}, {%0,%1,%2,%3};"
                        : "+f"(acc[mt][nt][0]), "+f"(acc[mt][nt][1]),
                          "+f"(acc[mt][nt][2]), "+f"(acc[mt][nt][3])
                        : "r"(af[mt][0]), "r"(af[mt][1]), "r"(af[mt][2]), "r"(af[mt][3]),
                          "r"(bf[nt][0]), "r"(bf[nt][1]));
                }
        }
    }

    const int g = lane >> 2, t4 = lane & 3;
    #pragma unroll
    for (int mt = 0; mt < 2; mt++) {
        #pragma unroll
        for (int nt = 0; nt < 8; nt++) {
            int col = wn + nt*8 + 2*t4;
            #pragma unroll
            for (int h = 0; h < 2; h++) {
                int row = m0 + wm + mt*16 + g + h*8;
                if (row >= N_NODES) continue;
                float2 zs = *(const float2*)&zself[(size_t)row * DIM + col];
                float2 o;
                o.x = silu_f(acc[mt][nt][h*2 + 0] + zs.x);
                o.y = silu_f(acc[mt][nt][h*2 + 1] + zs.y);
                *(float2*)&outz[(size_t)row * DIM + col] = o;
            }
        }
    }
}

// ---------------- shared mma helper: 32x64 warp tile over K=128 in smem ---
__device__ __forceinline__ void mma_k128(
    const __half (*Amat)[136], const __half (*Bmat)[136],
    int wm, int wn, int lane, float acc[2][8][4])
{
    #pragma unroll
    for (int kc = 0; kc < 128; kc += 16) {
        unsigned af[2][4];
        #pragma unroll
        for (int mt = 0; mt < 2; mt++) {
            const __half* p = &Amat[wm + mt*16 + (lane & 15)][kc + ((lane >> 4) << 3)];
            unsigned addr = (unsigned)__cvta_generic_to_shared(p);
            asm volatile("ldmatrix.sync.aligned.m8n8.x4.shared.b16 {%0,%1,%2,%3}, [%4];"
                : "=r"(af[mt][0]), "=r"(af[mt][1]), "=r"(af[mt][2]), "=r"(af[mt][3])
                : "r"(addr));
        }
        unsigned bf[8][2];
        #pragma unroll
        for (int q = 0; q < 4; q++) {
            const __half* p = &Bmat[kc + (lane & 15)][wn + q*16 + ((lane >> 4) << 3)];
            unsigned addr = (unsigned)__cvta_generic_to_shared(p);
            asm volatile("ldmatrix.sync.aligned.m8n8.x4.trans.shared.b16 {%0,%1,%2,%3}, [%4];"
                : "=r"(bf[q*2][0]), "=r"(bf[q*2][1]), "=r"(bf[q*2+1][0]), "=r"(bf[q*2+1][1])
                : "r"(addr));
        }
        #pragma unroll
        for (int mt = 0; mt < 2; mt++)
            #pragma unroll
            for (int nt = 0; nt < 8; nt++) {
                asm volatile(
                    "mma.sync.aligned.m16n8k16.row.col.f32.f16.f16.f32 "
                    "{%0,%1,%2,%3}, {%4,%5,%6,%7}, {%8,%9}, {%0,%1,%2,%3};"
                    : "+f"(acc[mt][nt][0]), "+f"(acc[mt][nt][1]),
                      "+f"(acc[mt][nt][2]), "+f"(acc[mt][nt][3])
                    : "r"(af[mt][0]), "r"(af[mt][1]), "r"(af[mt][2]), "r"(af[mt][3]),
                      "r"(bf[nt][0]), "r"(bf[nt][1]));
            }
    }
}

// ---------------- fused onsite block: zi = A + silu(A@Wa+ba)@Wb + bb ------
// STORE: 0 = only zi; 1 = also out[N*128 + row*256 + col] (layer0 final);
//        2 = also out[row*128+col] and out[N*128 + row*256 + 128 + col] (layer1 final).
template<int STORE>
__global__ __launch_bounds__(256) void k_onsite(
    const float* __restrict__ in, const __half* __restrict__ Wa,
    const float* __restrict__ ba, const __half* __restrict__ Wb,
    const float* __restrict__ bb, float* __restrict__ outz,
    float* __restrict__ out2)
{
    extern __shared__ __half sm_h[];
    __half (*As)[136] = (__half(*)[136])sm_h;
    __half (*Ws)[136] = (__half(*)[136])(sm_h + 128*136);
    __half (*Hs)[136] = (__half(*)[136])(sm_h + 2*128*136);

    const int t = threadIdx.x;
    const int warp = t >> 5, lane = t & 31;
    const int wm = (warp & 3) * 32, wn = (warp >> 2) * 64;
    const int m0 = blockIdx.x * 128;
    const int r = t >> 1, c0 = (t & 1) * 64;
    const int gm = m0 + r;

    #pragma unroll
    for (int i = 0; i < 16; i++) {
        float4 v = make_float4(0.f,0.f,0.f,0.f);
        if (gm < N_NODES) v = *(const float4*)&in[(size_t)gm * DIM + c0 + i*4];
        *(__half2*)&As[r][c0 + i*4]     = __floats2half2_rn(v.x, v.y);
        *(__half2*)&As[r][c0 + i*4 + 2] = __floats2half2_rn(v.z, v.w);
    }
    #pragma unroll
    for (int i = 0; i < 8; i++)
        *(uint4*)&Ws[r][c0 + i*8] = *(const uint4*)&Wa[r * DIM + c0 + i*8];
    __syncthreads();

    float acc[2][8][4];
    #pragma unroll
    for (int mt = 0; mt < 2; mt++)
        #pragma unroll
        for (int nt = 0; nt < 8; nt++)
            #pragma unroll
            for (int i = 0; i < 4; i++) acc[mt][nt][i] = 0.0f;

    mma_k128(As, Ws, wm, wn, lane, acc);

    const int g4 = lane >> 2, t4 = lane & 3;
    #pragma unroll
    for (int mt = 0; mt < 2; mt++) {
        #pragma unroll
        for (int nt = 0; nt < 8; nt++) {
            int col = wn + nt*8 + 2*t4;
            float b0 = ba[col], b1 = ba[col + 1];
            int r0 = wm + mt*16 + g4;
            *(__half2*)&Hs[r0][col] =
                __floats2half2_rn(silu_f(acc[mt][nt][0] + b0), silu_f(acc[mt][nt][1] + b1));
            *(__half2*)&Hs[r0 + 8][col] =
                __floats2half2_rn(silu_f(acc[mt][nt][2] + b0), silu_f(acc[mt][nt][3] + b1));
        }
    }
    __syncthreads();
    #pragma unroll
    for (int i = 0; i < 8; i++)
        *(uint4*)&Ws[r][c0 + i*8] = *(const uint4*)&Wb[r * DIM + c0 + i*8];
    __syncthreads();

    #pragma unroll
    for (int mt = 0; mt < 2; mt++)
        #pragma unroll
        for (int nt = 0; nt < 8; nt++)
            #pragma unroll
            for (int i = 0; i < 4; i++) acc[mt][nt][i] = 0.0f;

    mma_k128(Hs, Ws, wm, wn, lane, acc);

    #pragma unroll
    for (int mt = 0; mt < 2; mt++) {
        #pragma unroll
        for (int nt = 0; nt < 8; nt++) {
            int col = wn + nt*8 + 2*t4;
            float b0 = bb[col], b1 = bb[col + 1];
            #pragma unroll
            for (int h = 0; h < 2; h++) {
                int row = m0 + wm + mt*16 + g4 + h*8;
                if (row >= N_NODES) continue;
                float2 rv = *(const float2*)&in[(size_t)row * DIM + col];
                float2 o;
                o.x = acc[mt][nt][h*2 + 0] + b0 + rv.x;
                o.y = acc[mt][nt][h*2 + 1] + b1 + rv.y;
                *(float2*)&outz[(size_t)row * DIM + col] = o;
                if (STORE == 1) {
                    *(float2*)&out2[(size_t)N_NODES * DIM + (size_t)row * 2 * DIM + col] = o;
                } else if (STORE == 2) {
                    *(float2*)&out2[(size_t)row * DIM + col] = o;
                    *(float2*)&out2[(size_t)N_NODES * DIM + (size_t)row * 2 * DIM + DIM + col] = o;
                }
            }
        }
    }
}

// ---------------- host driver ----------------
extern "C" void kernel_launch(void* const* d_in, const int* in_sizes, int n_in,
                              void* d_out, int out_size)
{
    const int*   species = (const int*)  d_in[0];
    const int*   esrc    = (const int*)  d_in[1];
    const int*   edst    = (const int*)  d_in[2];
    const float* dist    = (const float*)d_in[3];
    const float* swp     = (const float*)d_in[4];
    const float* Z       = (const float*)d_in[5];
    const float* Ws0     = (const float*)d_in[6];
    const float* bs0     = (const float*)d_in[7];
    const float* V0      = (const float*)d_in[8];
    const float* Ws1     = (const float*)d_in[9];
    const float* bs1     = (const float*)d_in[10];
    const float* V1      = (const float*)d_in[11];
    const float* Won_a   = (const float*)d_in[12];
    const float* bon_a   = (const float*)d_in[13];
    const float* Won_b   = (const float*)d_in[14];
    const float* bon_b   = (const float*)d_in[15];
    float* out = (float*)d_out;

    float *zi16, *zi, *zself;
    __half *Ah, *Vh0, *Vh1, *Wah, *Wbh;
    cudaGetSymbolAddress((void**)&zi16,  g_zi16);
    cudaGetSymbolAddress((void**)&zi,    g_zi);
    cudaGetSymbolAddress((void**)&zself, g_zself);
    cudaGetSymbolAddress((void**)&Ah,    g_A);
    cudaGetSymbolAddress((void**)&Vh0,   g_Vh0);
    cudaGetSymbolAddress((void**)&Vh1,   g_Vh1);
    cudaGetSymbolAddress((void**)&Wah,   g_Wah);
    cudaGetSymbolAddress((void**)&Wbh,   g_Wbh);

    const int MB = (N_NODES + 127) / 128;       // 157
    dim3 gemm128(1,  MB);
    const int EB = (N_EDGES + 255) / 256;
    const int NBK = (N_NODES + 7) / 8;

    const int SCAN_SMEM   = (N_NODES + 1024) * (int)sizeof(int);     // ~84 KB
    const int ONSITE_SMEM = 3 * 128 * 136 * (int)sizeof(__half);     // ~104 KB
    static int attr_done = 0;
    if (!attr_done) {
        cudaFuncSetAttribute(k_scan_fast, cudaFuncAttributeMaxDynamicSharedMemorySize, SCAN_SMEM);
        cudaFuncSetAttribute(k_onsite<0>, cudaFuncAttributeMaxDynamicSharedMemorySize, ONSITE_SMEM);
        cudaFuncSetAttribute(k_onsite<1>, cudaFuncAttributeMaxDynamicSharedMemorySize, ONSITE_SMEM);
        cudaFuncSetAttribute(k_onsite<2>, cudaFuncAttributeMaxDynamicSharedMemorySize, ONSITE_SMEM);
        attr_done = 1;
    }

    // ---- preprocessing ----
    k_embed<<<(N_NODES * ZD + 255) / 256, 256>>>(species, Z);
    k_zero_deg<<<(N_NODES + 255) / 256, 256>>>();
    k_count<<<EB, 256>>>(esrc);
    k_scan_fast<<<1, 1024, SCAN_SMEM>>>();
    k_fillS<<<EB, 256>>>(esrc, edst, dist, swp);
    k_f2h<<<(KT0 * DIM + 255) / 256, 256>>>(V0, Vh0, KT0 * DIM);
    k_f2h<<<(KT1 * DIM + 255) / 256, 256>>>(V1, Vh1, KT1 * DIM);
    k_wconv<<<(NLAYERS * 3 * DIM * DIM + 255) / 256, 256>>>(Won_a, Won_b);

    // ---- layer 0 ----
    k_gemm2<<<gemm128, 256>>>(zi16, Ws0, bs0, zself, N_NODES, ZD, ZD, DIM, DIM);
    k_edgeT0<<<NBK, 256>>>();
    k_hgemmE<<<MB, 256>>>(Ah, Vh0, zself, zi, KT0);

    k_onsite<0><<<MB, 256, ONSITE_SMEM>>>(zi,
        Wah + 0*DIM*DIM, bon_a + 0*DIM, Wbh + 0*DIM*DIM, bon_b + 0*DIM, zi, out);
    k_onsite<0><<<MB, 256, ONSITE_SMEM>>>(zi,
        Wah + 1*DIM*DIM, bon_a + 1*DIM, Wbh + 1*DIM*DIM, bon_b + 1*DIM, zi, out);
    k_onsite<1><<<MB, 256, ONSITE_SMEM>>>(zi,
        Wah + 2*DIM*DIM, bon_a + 2*DIM, Wbh + 2*DIM*DIM, bon_b + 2*DIM, zi, out);

    // ---- layer 1 ----
    k_gemm2<<<gemm128, 256>>>(zi, Ws1, bs1, zself, N_NODES, DIM, DIM, DIM, DIM);
    k_edgeT1<<<NBK, 256>>>();
    k_hgemmE<<<MB, 256>>>(Ah, Vh1, zself, zi, KT1);

    k_onsite<0><<<MB, 256, ONSITE_SMEM>>>(zi,
        Wah + 3*DIM*DIM, bon_a + 3*DIM, Wbh + 3*DIM*DIM, bon_b + 3*DIM, zi, out);
    k_onsite<0><<<MB, 256, ONSITE_SMEM>>>(zi,
        Wah + 4*DIM*DIM, bon_a + 4*DIM, Wbh + 4*DIM*DIM, bon_b + 4*DIM, zi, out);
    k_onsite<2><<<MB, 256, ONSITE_SMEM>>>(zi,
        Wah + 5*DIM*DIM, bon_a + 5*DIM, Wbh + 5*DIM*DIM, bon_b + 5*DIM, zi, out);
}

// round 7
// speedup vs baseline: 1.9358x; 1.0963x over previous
#include <cuda_runtime.h>
#include <cuda_fp16.h>
#include <math.h>

#define N_NODES 20000
#define N_EDGES 400000
#define DIM 128
#define NB 16
#define ZD 16
#define NLAYERS 2
#define KT1 (NB*DIM)   // 2048
#define KT0 (NB*ZD)    // 256
#define SCAN_BLKS ((N_NODES + 255) / 256)   // 79

// ---------------- device scratch (static, no allocations) ----------------
__device__ float  g_zi16[N_NODES*ZD];
__device__ float  g_zi[N_NODES*DIM];
__device__ float  g_zself[N_NODES*DIM];
__device__ __half g_A[(size_t)N_NODES*KT1];     // aggregated T rows (fp16)
__device__ __half g_Vh0[KT0*DIM];               // V0.reshape(-1,128) fp16
__device__ __half g_Vh1[KT1*DIM];               // V1.reshape(-1,128) fp16
__device__ __half g_Wah[NLAYERS*3*DIM*DIM];     // onsite Wa fp16
__device__ __half g_Wbh[NLAYERS*3*DIM*DIM];     // onsite Wb fp16

// CSR by src + reordered edge data
__device__ int   g_degS[N_NODES], g_offS[N_NODES+1], g_curS[N_NODES];
__device__ int   g_part[128];
__device__ int   g_dstS[N_EDGES];
__device__ float g_distS[N_EDGES];
__device__ float g_swS[N_EDGES];

__device__ __forceinline__ float silu_f(float x) {
    return x / (1.0f + __expf(-x));
}

// ---------------- merged preprocessing ----------------
__global__ void k_prep(const int* __restrict__ species, const float* __restrict__ Z,
                       const float* __restrict__ V0, const float* __restrict__ V1,
                       const float* __restrict__ Wa, const float* __restrict__ Wb)
{
    int t = blockIdx.x * blockDim.x + threadIdx.x;
    if (t < N_NODES * ZD) {
        int n = t >> 4, k = t & 15;
        g_zi16[t] = Z[species[n] * ZD + k];
    }
    if (t < KT1 * DIM) g_Vh1[t] = __float2half(V1[t]);
    if (t < KT0 * DIM) g_Vh0[t] = __float2half(V0[t]);
    if (t < NLAYERS * 3 * DIM * DIM) {
        g_Wah[t] = __float2half(Wa[t]);
        g_Wbh[t] = __float2half(Wb[t]);
    }
    if (t < N_NODES) g_degS[t] = 0;
}

// ---------------- CSR build (by src), parallel scan ----------------
__global__ void k_count(const int* __restrict__ esrc) {
    int e = blockIdx.x * blockDim.x + threadIdx.x;
    if (e < N_EDGES) atomicAdd(&g_degS[esrc[e]], 1);
}
__global__ void k_scan1() {
    __shared__ int s[256];
    int t = threadIdx.x, idx = blockIdx.x * 256 + t;
    s[t] = (idx < N_NODES) ? g_degS[idx] : 0;
    __syncthreads();
    #pragma unroll
    for (int d = 128; d > 0; d >>= 1) {
        if (t < d) s[t] += s[t + d];
        __syncthreads();
    }
    if (t == 0) g_part[blockIdx.x] = s[0];
}
__global__ void k_scan2() {
    __shared__ int s[128];
    int t = threadIdx.x;
    int v = (t < SCAN_BLKS) ? g_part[t] : 0;
    s[t] = v;
    __syncthreads();
    #pragma unroll
    for (int d = 1; d < 128; d <<= 1) {
        int x = (t >= d) ? s[t - d] : 0;
        __syncthreads();
        s[t] += x;
        __syncthreads();
    }
    if (t < SCAN_BLKS) g_part[t] = s[t] - v;      // exclusive base per block
    if (t == 127) g_offS[N_NODES] = s[127];       // total
}
__global__ void k_scan3() {
    __shared__ int s[256];
    int t = threadIdx.x, idx = blockIdx.x * 256 + t;
    int v = (idx < N_NODES) ? g_degS[idx] : 0;
    s[t] = v;
    __syncthreads();
    #pragma unroll
    for (int d = 1; d < 256; d <<= 1) {
        int x = (t >= d) ? s[t - d] : 0;
        __syncthreads();
        s[t] += x;
        __syncthreads();
    }
    int excl = s[t] - v + g_part[blockIdx.x];
    if (idx < N_NODES) {
        g_offS[idx] = excl;
        g_curS[idx] = excl;
    }
}
__global__ void k_fillS(const int* __restrict__ esrc, const int* __restrict__ edst,
                        const float* __restrict__ dist, const float* __restrict__ sw) {
    int e = blockIdx.x * blockDim.x + threadIdx.x;
    if (e < N_EDGES) {
        int pos = atomicAdd(&g_curS[esrc[e]], 1);
        g_dstS[pos]  = edst[e];
        g_distS[pos] = dist[e];
        g_swS[pos]   = sw[e];
    }
}

// ---------------- fp32 SGEMM (zself): BM=BN=128, 8x8/thread ---------------
__global__ __launch_bounds__(256, 2) void k_gemm2(
    const float* __restrict__ A, const float* __restrict__ B,
    const float* __restrict__ bias, float* __restrict__ C,
    int M, int K, int lda, int ldb, int ldc)
{
    __shared__ float As[16][136];
    __shared__ float Bs[16][128];

    const int t    = threadIdx.x;
    const int warp = t >> 5, lane = t & 31;
    const int wr = warp & 3, wc = warp >> 2;
    const int lr = lane >> 3, lc = lane & 7;
    const int row0 = wr * 32 + lr * 8;
    const int col0 = wc * 64 + lc * 8;
    const int m0 = blockIdx.y * 128, n0 = blockIdx.x * 128;

    const int arow = t >> 1;
    const int ak   = (t & 1) * 8;
    const int brow = t >> 4;
    const int bcol = (t & 15) * 8;

    float acc[8][8];
    #pragma unroll
    for (int i = 0; i < 8; i++)
        #pragma unroll
        for (int j = 0; j < 8; j++) acc[i][j] = 0.0f;

    for (int k0 = 0; k0 < K; k0 += 16) {
        float4 a0 = make_float4(0.f,0.f,0.f,0.f), a1 = a0;
        const int gm = m0 + arow;
        if (gm < M) {
            a0 = *(const float4*)&A[(size_t)gm * lda + k0 + ak];
            a1 = *(const float4*)&A[(size_t)gm * lda + k0 + ak + 4];
        }
        float4 b0 = *(const float4*)&B[(size_t)(k0 + brow) * ldb + n0 + bcol];
        float4 b1 = *(const float4*)&B[(size_t)(k0 + brow) * ldb + n0 + bcol + 4];

        __syncthreads();
        As[ak+0][arow] = a0.x; As[ak+1][arow] = a0.y;
        As[ak+2][arow] = a0.z; As[ak+3][arow] = a0.w;
        As[ak+4][arow] = a1.x; As[ak+5][arow] = a1.y;
        As[ak+6][arow] = a1.z; As[ak+7][arow] = a1.w;
        *(float4*)&Bs[brow][bcol]     = b0;
        *(float4*)&Bs[brow][bcol + 4] = b1;
        __syncthreads();

        #pragma unroll
        for (int kk = 0; kk < 16; kk++) {
            float4 x0 = *(float4*)&As[kk][row0];
            float4 x1 = *(float4*)&As[kk][row0 + 4];
            float4 y0 = *(float4*)&Bs[kk][col0];
            float4 y1 = *(float4*)&Bs[kk][col0 + 4];
            float ar[8] = {x0.x,x0.y,x0.z,x0.w,x1.x,x1.y,x1.z,x1.w};
            float br[8] = {y0.x,y0.y,y0.z,y0.w,y1.x,y1.y,y1.z,y1.w};
            #pragma unroll
            for (int i = 0; i < 8; i++)
                #pragma unroll
                for (int j = 0; j < 8; j++)
                    acc[i][j] += ar[i] * br[j];
        }
    }

    #pragma unroll
    for (int i = 0; i < 8; i++) {
        int m = m0 + row0 + i;
        if (m >= M) continue;
        float v[8];
        #pragma unroll
        for (int j = 0; j < 8; j++) v[j] = acc[i][j] + bias[n0 + col0 + j];
        float* cp = &C[(size_t)m * ldc + n0 + col0];
        ((float4*)cp)[0] = make_float4(v[0], v[1], v[2], v[3]);
        ((float4*)cp)[1] = make_float4(v[4], v[5], v[6], v[7]);
    }
}

// ---------------- edge aggregation: T[n] = sum_{e:src=n} s_e x z_dst ------
__global__ __launch_bounds__(256) void k_edgeT1() {
    const int warp = threadIdx.x >> 5;
    const int lane = threadIdx.x & 31;
    const int n = blockIdx.x * 8 + warp;
    if (n >= N_NODES) return;

    float acc[16][4];
    #pragma unroll
    for (int b = 0; b < 16; b++)
        #pragma unroll
        for (int i = 0; i < 4; i++) acc[b][i] = 0.0f;

    const int p0 = g_offS[n], p1 = g_offS[n + 1];
    const float sigma  = 0.8f / 15.0f;
    const float rsigma = 15.0f / 0.8f;
    const float mu_l   = 0.2f + (float)(lane & 15) * sigma;

    for (int p = p0; p < p1; p++) {
        const int dst = g_dstS[p];
        const float di = g_distS[p];
        const float sw = g_swS[p];
        float rinv = 1.0f / di;
        float x = (rinv - mu_l) * rsigma;
        float sv = __expf(-0.5f * x * x) * sw;

        float4 zv = *(const float4*)&g_zi[(size_t)dst * DIM + lane * 4];
        #pragma unroll
        for (int b = 0; b < 16; b++) {
            float sb = __shfl_sync(0xffffffffu, sv, b);
            acc[b][0] += sb * zv.x;
            acc[b][1] += sb * zv.y;
            acc[b][2] += sb * zv.z;
            acc[b][3] += sb * zv.w;
        }
    }

    __half* Ap = g_A + (size_t)n * KT1;
    #pragma unroll
    for (int b = 0; b < 16; b++) {
        __half2 h0 = __floats2half2_rn(acc[b][0], acc[b][1]);
        __half2 h1 = __floats2half2_rn(acc[b][2], acc[b][3]);
        uint2 st;
        st.x = *(unsigned*)&h0;
        st.y = *(unsigned*)&h1;
        *(uint2*)&Ap[b * DIM + lane * 4] = st;
    }
}

__global__ __launch_bounds__(256) void k_edgeT0() {
    const int warp = threadIdx.x >> 5;
    const int lane = threadIdx.x & 31;
    const int n = blockIdx.x * 8 + warp;
    if (n >= N_NODES) return;

    float acc[8];
    #pragma unroll
    for (int j = 0; j < 8; j++) acc[j] = 0.0f;

    const int p0 = g_offS[n], p1 = g_offS[n + 1];
    const int k  = lane & 15;
    const int bb = (lane >> 4) * 8;
    const float sigma  = 0.8f / 15.0f;
    const float rsigma = 15.0f / 0.8f;
    const float mu_l   = 0.2f + (float)k * sigma;

    for (int p = p0; p < p1; p++) {
        const int dst = g_dstS[p];
        const float di = g_distS[p];
        const float sw = g_swS[p];
        float rinv = 1.0f / di;
        float x = (rinv - mu_l) * rsigma;
        float sv = __expf(-0.5f * x * x) * sw;

        float zv = g_zi16[dst * ZD + k];
        #pragma unroll
        for (int j = 0; j < 8; j++) {
            float sb = __shfl_sync(0xffffffffu, sv, bb + j);
            acc[j] += sb * zv;
        }
    }

    __half* Ap = g_A + (size_t)n * KT0;
    #pragma unroll
    for (int j = 0; j < 8; j++)
        Ap[(bb + j) * ZD + k] = __float2half(acc[j]);
}

// ---------------- TC GEMM + epilogue, cp.async double-buffered ------------
// zi = silu(T @ Vflat + zself). M=20000, N=128, K in {256, 2048}.
#define CPA16(dst, src, bytes) \
    asm volatile("cp.async.cg.shared.global [%0], [%1], 16, %2;" \
                 :: "r"(dst), "l"(src), "r"(bytes))

__global__ __launch_bounds__(256, 2) void k_hgemmE(
    const __half* __restrict__ A, const __half* __restrict__ B,
    const float* __restrict__ zself, float* __restrict__ outz, int K)
{
    __shared__ __half As[2][128][40];
    __shared__ __half Bs[2][32][136];

    const int t    = threadIdx.x;
    const int warp = t >> 5, lane = t & 31;
    const int wm = (warp & 3) * 32;
    const int wn = (warp >> 2) * 64;
    const int m0 = blockIdx.x * 128;

    const int arow = t >> 1, ak = (t & 1) * 8;
    const int brow = t >> 4, bcol = (t & 15) * 8;
    const int gm = m0 + arow;
    const int apred = (gm < N_NODES) ? 16 : 0;
    const __half* Abase = &A[(size_t)gm * K];

    float acc[2][8][4];
    #pragma unroll
    for (int mt = 0; mt < 2; mt++)
        #pragma unroll
        for (int nt = 0; nt < 8; nt++)
            #pragma unroll
            for (int i = 0; i < 4; i++) acc[mt][nt][i] = 0.0f;

    const int T = K >> 5;

    // prologue: issue tile 0 into buf 0
    {
        unsigned da0 = (unsigned)__cvta_generic_to_shared(&As[0][arow][ak]);
        unsigned da1 = (unsigned)__cvta_generic_to_shared(&As[0][arow][16 + ak]);
        CPA16(da0, Abase + ak, apred);
        CPA16(da1, Abase + 16 + ak, apred);
        unsigned db0 = (unsigned)__cvta_generic_to_shared(&Bs[0][brow][bcol]);
        unsigned db1 = (unsigned)__cvta_generic_to_shared(&Bs[0][16 + brow][bcol]);
        CPA16(db0, &B[(size_t)brow * DIM + bcol], 16);
        CPA16(db1, &B[(size_t)(16 + brow) * DIM + bcol], 16);
        asm volatile("cp.async.commit_group;");
    }

    for (int tt = 0; tt < T; tt++) {
        if (tt + 1 < T) {
            const int buf = (tt + 1) & 1, k0 = (tt + 1) * 32;
            unsigned da0 = (unsigned)__cvta_generic_to_shared(&As[buf][arow][ak]);
            unsigned da1 = (unsigned)__cvta_generic_to_shared(&As[buf][arow][16 + ak]);
            CPA16(da0, Abase + k0 + ak, apred);
            CPA16(da1, Abase + k0 + 16 + ak, apred);
            unsigned db0 = (unsigned)__cvta_generic_to_shared(&Bs[buf][brow][bcol]);
            unsigned db1 = (unsigned)__cvta_generic_to_shared(&Bs[buf][16 + brow][bcol]);
            CPA16(db0, &B[(size_t)(k0 + brow) * DIM + bcol], 16);
            CPA16(db1, &B[(size_t)(k0 + 16 + brow) * DIM + bcol], 16);
            asm volatile("cp.async.commit_group;");
            asm volatile("cp.async.wait_group 1;");
        } else {
            asm volatile("cp.async.wait_group 0;");
        }
        __syncthreads();

        const int buf = tt & 1;
        #pragma unroll
        for (int sub = 0; sub < 2; sub++) {
            const int kc = sub * 16;
            unsigned af[2][4];
            #pragma unroll
            for (int mt = 0; mt < 2; mt++) {
                const __half* p = &As[buf][wm + mt*16 + (lane & 15)][kc + ((lane >> 4) << 3)];
                unsigned addr = (unsigned)__cvta_generic_to_shared(p);
                asm volatile("ldmatrix.sync.aligned.m8n8.x4.shared.b16 {%0,%1,%2,%3}, [%4];"
                    : "=r"(af[mt][0]), "=r"(af[mt][1]), "=r"(af[mt][2]), "=r"(af[mt][3])
                    : "r"(addr));
            }
            unsigned bf[8][2];
            #pragma unroll
            for (int q = 0; q < 4; q++) {
                const __half* p = &Bs[buf][kc + (lane & 15)][wn + q*16 + ((lane >> 4) << 3)];
                unsigned addr = (unsigned)__cvta_generic_to_shared(p);
                asm volatile("ldmatrix.sync.aligned.m8n8.x4.trans.shared.b16 {%0,%1,%2,%3}, [%4];"
                    : "=r"(bf[q*2][0]), "=r"(bf[q*2][1]), "=r"(bf[q*2+1][0]), "=r"(bf[q*2+1][1])
                    : "r"(addr));
            }
            #pragma unroll
            for (int mt = 0; mt < 2; mt++)
                #pragma unroll
                for (int nt = 0; nt < 8; nt++) {
                    asm volatile(
                        "mma.sync.aligned.m16n8k16.row.col.f32.f16.f16.f32 "
                        "{%0,%1,%2,%3}, {%4,%5,%6,%7}, {%8,%9}, {%0,%1,%2,%3};"
                        : "+f"(acc[mt][nt][0]), "+f"(acc[mt][nt][1]),
                          "+f"(acc[mt][nt][2]), "+f"(acc[mt][nt][3])
                        : "r"(af[mt][0]), "r"(af[mt][1]), "r"(af[mt][2]), "r"(af[mt][3]),
                          "r"(bf[nt][0]), "r"(bf[nt][1]));
                }
        }
        __syncthreads();
    }

    const int g = lane >> 2, t4 = lane & 3;
    #pragma unroll
    for (int mt = 0; mt < 2; mt++) {
        #pragma unroll
        for (int nt = 0; nt < 8; nt++) {
            int col = wn + nt*8 + 2*t4;
            #pragma unroll
            for (int h = 0; h < 2; h++) {
                int row = m0 + wm + mt*16 + g + h*8;
                if (row >= N_NODES) continue;
                float2 zs = *(const float2*)&zself[(size_t)row * DIM + col];
                float2 o;
                o.x = silu_f(acc[mt][nt][h*2 + 0] + zs.x);
                o.y = silu_f(acc[mt][nt][h*2 + 1] + zs.y);
                *(float2*)&outz[(size_t)row * DIM + col] = o;
            }
        }
    }
}

// ---------------- shared mma helper: 32x64 warp tile over K=128 in smem ---
__device__ __forceinline__ void mma_k128(
    const __half (*Amat)[136], const __half (*Bmat)[136],
    int wm, int wn, int lane, float acc[2][8][4])
{
    #pragma unroll
    for (int kc = 0; kc < 128; kc += 16) {
        unsigned af[2][4];
        #pragma unroll
        for (int mt = 0; mt < 2; mt++) {
            const __half* p = &Amat[wm + mt*16 + (lane & 15)][kc + ((lane >> 4) << 3)];
            unsigned addr = (unsigned)__cvta_generic_to_shared(p);
            asm volatile("ldmatrix.sync.aligned.m8n8.x4.shared.b16 {%0,%1,%2,%3}, [%4];"
                : "=r"(af[mt][0]), "=r"(af[mt][1]), "=r"(af[mt][2]), "=r"(af[mt][3])
                : "r"(addr));
        }
        unsigned bf[8][2];
        #pragma unroll
        for (int q = 0; q < 4; q++) {
            const __half* p = &Bmat[kc + (lane & 15)][wn + q*16 + ((lane >> 4) << 3)];
            unsigned addr = (unsigned)__cvta_generic_to_shared(p);
            asm volatile("ldmatrix.sync.aligned.m8n8.x4.trans.shared.b16 {%0,%1,%2,%3}, [%4];"
                : "=r"(bf[q*2][0]), "=r"(bf[q*2][1]), "=r"(bf[q*2+1][0]), "=r"(bf[q*2+1][1])
                : "r"(addr));
        }
        #pragma unroll
        for (int mt = 0; mt < 2; mt++)
            #pragma unroll
            for (int nt = 0; nt < 8; nt++) {
                asm volatile(
                    "mma.sync.aligned.m16n8k16.row.col.f32.f16.f16.f32 "
                    "{%0,%1,%2,%3}, {%4,%5,%6,%7}, {%8,%9}, {%0,%1,%2,%3};"
                    : "+f"(acc[mt][nt][0]), "+f"(acc[mt][nt][1]),
                      "+f"(acc[mt][nt][2]), "+f"(acc[mt][nt][3])
                    : "r"(af[mt][0]), "r"(af[mt][1]), "r"(af[mt][2]), "r"(af[mt][3]),
                      "r"(bf[nt][0]), "r"(bf[nt][1]));
            }
    }
}

// ---------------- fused onsite block (Hs aliases As; 68KB smem) -----------
// STORE: 0 = only zi; 1 = also out zis[layer0]; 2 = also out final + zis[layer1].
template<int STORE>
__global__ __launch_bounds__(256) void k_onsite(
    const float* __restrict__ in, const __half* __restrict__ Wa,
    const float* __restrict__ ba, const __half* __restrict__ Wb,
    const float* __restrict__ bb, float* __restrict__ outz,
    float* __restrict__ out2)
{
    extern __shared__ __half sm_h[];
    __half (*As)[136] = (__half(*)[136])sm_h;                  // A tile, later H tile
    __half (*Ws)[136] = (__half(*)[136])(sm_h + 128*136);      // Wa, later Wb

    const int t = threadIdx.x;
    const int warp = t >> 5, lane = t & 31;
    const int wm = (warp & 3) * 32, wn = (warp >> 2) * 64;
    const int m0 = blockIdx.x * 128;
    const int r = t >> 1, c0 = (t & 1) * 64;
    const int gm = m0 + r;

    #pragma unroll
    for (int i = 0; i < 16; i++) {
        float4 v = make_float4(0.f,0.f,0.f,0.f);
        if (gm < N_NODES) v = *(const float4*)&in[(size_t)gm * DIM + c0 + i*4];
        *(__half2*)&As[r][c0 + i*4]     = __floats2half2_rn(v.x, v.y);
        *(__half2*)&As[r][c0 + i*4 + 2] = __floats2half2_rn(v.z, v.w);
    }
    #pragma unroll
    for (int i = 0; i < 8; i++)
        *(uint4*)&Ws[r][c0 + i*8] = *(const uint4*)&Wa[r * DIM + c0 + i*8];
    __syncthreads();

    float acc[2][8][4];
    #pragma unroll
    for (int mt = 0; mt < 2; mt++)
        #pragma unroll
        for (int nt = 0; nt < 8; nt++)
            #pragma unroll
            for (int i = 0; i < 4; i++) acc[mt][nt][i] = 0.0f;

    mma_k128(As, Ws, wm, wn, lane, acc);
    __syncthreads();   // all warps done reading As/Ws before overwrite

    // epilogue 1: H = silu(acc + ba) -> As region; reload Ws with Wb
    const int g4 = lane >> 2, t4 = lane & 3;
    #pragma unroll
    for (int mt = 0; mt < 2; mt++) {
        #pragma unroll
        for (int nt = 0; nt < 8; nt++) {
            int col = wn + nt*8 + 2*t4;
            float b0 = ba[col], b1 = ba[col + 1];
            int r0 = wm + mt*16 + g4;
            *(__half2*)&As[r0][col] =
                __floats2half2_rn(silu_f(acc[mt][nt][0] + b0), silu_f(acc[mt][nt][1] + b1));
            *(__half2*)&As[r0 + 8][col] =
                __floats2half2_rn(silu_f(acc[mt][nt][2] + b0), silu_f(acc[mt][nt][3] + b1));
        }
    }
    #pragma unroll
    for (int i = 0; i < 8; i++)
        *(uint4*)&Ws[r][c0 + i*8] = *(const uint4*)&Wb[r * DIM + c0 + i*8];
    __syncthreads();

    #pragma unroll
    for (int mt = 0; mt < 2; mt++)
        #pragma unroll
        for (int nt = 0; nt < 8; nt++)
            #pragma unroll
            for (int i = 0; i < 4; i++) acc[mt][nt][i] = 0.0f;

    mma_k128(As, Ws, wm, wn, lane, acc);

    #pragma unroll
    for (int mt = 0; mt < 2; mt++) {
        #pragma unroll
        for (int nt = 0; nt < 8; nt++) {
            int col = wn + nt*8 + 2*t4;
            float b0 = bb[col], b1 = bb[col + 1];
            #pragma unroll
            for (int h = 0; h < 2; h++) {
                int row = m0 + wm + mt*16 + g4 + h*8;
                if (row >= N_NODES) continue;
                float2 rv = *(const float2*)&in[(size_t)row * DIM + col];
                float2 o;
                o.x = acc[mt][nt][h*2 + 0] + b0 + rv.x;
                o.y = acc[mt][nt][h*2 + 1] + b1 + rv.y;
                *(float2*)&outz[(size_t)row * DIM + col] = o;
                if (STORE == 1) {
                    *(float2*)&out2[(size_t)N_NODES * DIM + (size_t)row * 2 * DIM + col] = o;
                } else if (STORE == 2) {
                    *(float2*)&out2[(size_t)row * DIM + col] = o;
                    *(float2*)&out2[(size_t)N_NODES * DIM + (size_t)row * 2 * DIM + DIM + col] = o;
                }
            }
        }
    }
}

// ---------------- host driver ----------------
extern "C" void kernel_launch(void* const* d_in, const int* in_sizes, int n_in,
                              void* d_out, int out_size)
{
    const int*   species = (const int*)  d_in[0];
    const int*   esrc    = (const int*)  d_in[1];
    const int*   edst    = (const int*)  d_in[2];
    const float* dist    = (const float*)d_in[3];
    const float* swp     = (const float*)d_in[4];
    const float* Z       = (const float*)d_in[5];
    const float* Ws0     = (const float*)d_in[6];
    const float* bs0     = (const float*)d_in[7];
    const float* V0      = (const float*)d_in[8];
    const float* Ws1     = (const float*)d_in[9];
    const float* bs1     = (const float*)d_in[10];
    const float* V1      = (const float*)d_in[11];
    const float* Won_a   = (const float*)d_in[12];
    const float* bon_a   = (const float*)d_in[13];
    const float* Won_b   = (const float*)d_in[14];
    const float* bon_b   = (const float*)d_in[15];
    float* out = (float*)d_out;

    float *zi16, *zi, *zself;
    __half *Ah, *Vh0, *Vh1, *Wah, *Wbh;
    cudaGetSymbolAddress((void**)&zi16,  g_zi16);
    cudaGetSymbolAddress((void**)&zi,    g_zi);
    cudaGetSymbolAddress((void**)&zself, g_zself);
    cudaGetSymbolAddress((void**)&Ah,    g_A);
    cudaGetSymbolAddress((void**)&Vh0,   g_Vh0);
    cudaGetSymbolAddress((void**)&Vh1,   g_Vh1);
    cudaGetSymbolAddress((void**)&Wah,   g_Wah);
    cudaGetSymbolAddress((void**)&Wbh,   g_Wbh);

    const int MB = (N_NODES + 127) / 128;       // 157
    dim3 gemm128(1,  MB);
    const int EB = (N_EDGES + 255) / 256;
    const int NBK = (N_NODES + 7) / 8;
    const int PREP_N = N_NODES * ZD;            // 320000, largest prep range

    const int ONSITE_SMEM = 2 * 128 * 136 * (int)sizeof(__half);  // 69632
    static int attr_done = 0;
    if (!attr_done) {
        cudaFuncSetAttribute(k_onsite<0>, cudaFuncAttributeMaxDynamicSharedMemorySize, ONSITE_SMEM);
        cudaFuncSetAttribute(k_onsite<1>, cudaFuncAttributeMaxDynamicSharedMemorySize, ONSITE_SMEM);
        cudaFuncSetAttribute(k_onsite<2>, cudaFuncAttributeMaxDynamicSharedMemorySize, ONSITE_SMEM);
        attr_done = 1;
    }

    // ---- preprocessing ----
    k_prep<<<(PREP_N + 255) / 256, 256>>>(species, Z, V0, V1, Won_a, Won_b);
    k_count<<<EB, 256>>>(esrc);
    k_scan1<<<SCAN_BLKS, 256>>>();
    k_scan2<<<1, 128>>>();
    k_scan3<<<SCAN_BLKS, 256>>>();
    k_fillS<<<EB, 256>>>(esrc, edst, dist, swp);

    // ---- layer 0 ----
    k_gemm2<<<gemm128, 256>>>(zi16, Ws0, bs0, zself, N_NODES, ZD, ZD, DIM, DIM);
    k_edgeT0<<<NBK, 256>>>();
    k_hgemmE<<<MB, 256>>>(Ah, Vh0, zself, zi, KT0);

    k_onsite<0><<<MB, 256, ONSITE_SMEM>>>(zi,
        Wah + 0*DIM*DIM, bon_a + 0*DIM, Wbh + 0*DIM*DIM, bon_b + 0*DIM, zi, out);
    k_onsite<0><<<MB, 256, ONSITE_SMEM>>>(zi,
        Wah + 1*DIM*DIM, bon_a + 1*DIM, Wbh + 1*DIM*DIM, bon_b + 1*DIM, zi, out);
    k_onsite<1><<<MB, 256, ONSITE_SMEM>>>(zi,
        Wah + 2*DIM*DIM, bon_a + 2*DIM, Wbh + 2*DIM*DIM, bon_b + 2*DIM, zi, out);

    // ---- layer 1 ----
    k_gemm2<<<gemm128, 256>>>(zi, Ws1, bs1, zself, N_NODES, DIM, DIM, DIM, DIM);
    k_edgeT1<<<NBK, 256>>>();
    k_hgemmE<<<MB, 256>>>(Ah, Vh1, zself, zi, KT1);

    k_onsite<0><<<MB, 256, ONSITE_SMEM>>>(zi,
        Wah + 3*DIM*DIM, bon_a + 3*DIM, Wbh + 3*DIM*DIM, bon_b + 3*DIM, zi, out);
    k_onsite<0><<<MB, 256, ONSITE_SMEM>>>(zi,
        Wah + 4*DIM*DIM, bon_a + 4*DIM, Wbh + 4*DIM*DIM, bon_b + 4*DIM, zi, out);
    k_onsite<2><<<MB, 256, ONSITE_SMEM>>>(zi,
        Wah + 5*DIM*DIM, bon_a + 5*DIM, Wbh + 5*DIM*DIM, bon_b + 5*DIM, zi, out);
}

// round 8
// speedup vs baseline: 2.0370x; 1.0523x over previous
#include <cuda_runtime.h>
#include <cuda_fp16.h>
#include <math.h>

#define N_NODES 20000
#define N_EDGES 400000
#define DIM 128
#define NB 16
#define ZD 16
#define NLAYERS 2
#define KT1 (NB*DIM)   // 2048
#define KT0 (NB*ZD)    // 256
#define SCAN_BLKS ((N_NODES + 255) / 256)   // 79

// ---------------- device scratch (static, no allocations) ----------------
__device__ float  g_zi[N_NODES*DIM];
__device__ __half g_A[(size_t)N_NODES*KT1];     // aggregated T rows (fp16)
__device__ __half g_z16h[N_NODES*32];           // layer0 features, padded K2=32
__device__ __half g_zih[N_NODES*DIM];           // fp16 copy of layer0 output
__device__ __half g_Vh0[KT0*DIM];               // V0.reshape(-1,128) fp16
__device__ __half g_Vh1[KT1*DIM];               // V1.reshape(-1,128) fp16
__device__ __half g_Ws0h[32*DIM];               // Ws0 padded to 32 rows, fp16
__device__ __half g_Ws1h[DIM*DIM];              // Ws1 fp16
__device__ __half g_Wah[NLAYERS*3*DIM*DIM];     // onsite Wa fp16
__device__ __half g_Wbh[NLAYERS*3*DIM*DIM];     // onsite Wb fp16

// CSR by src + reordered edge data
__device__ int   g_degS[N_NODES], g_offS[N_NODES+1], g_curS[N_NODES];
__device__ int   g_part[128];
__device__ int   g_dstS[N_EDGES];
__device__ float g_distS[N_EDGES];
__device__ float g_swS[N_EDGES];

__device__ __forceinline__ float silu_f(float x) {
    return x / (1.0f + __expf(-x));
}

// ---------------- merged preprocessing ----------------
__global__ void k_prep(const int* __restrict__ species, const float* __restrict__ Z,
                       const float* __restrict__ V0, const float* __restrict__ V1,
                       const float* __restrict__ Ws0, const float* __restrict__ Ws1,
                       const float* __restrict__ Wa, const float* __restrict__ Wb)
{
    int t = blockIdx.x * blockDim.x + threadIdx.x;
    if (t < N_NODES * 32) {
        int n = t >> 5, c = t & 31;
        g_z16h[t] = __float2half(c < ZD ? Z[species[n] * ZD + c] : 0.0f);
    }
    if (t < KT1 * DIM) g_Vh1[t] = __float2half(V1[t]);
    if (t < KT0 * DIM) g_Vh0[t] = __float2half(V0[t]);
    if (t < NLAYERS * 3 * DIM * DIM) {
        g_Wah[t] = __float2half(Wa[t]);
        g_Wbh[t] = __float2half(Wb[t]);
    }
    if (t < 32 * DIM) {
        int r = t >> 7;
        g_Ws0h[t] = __float2half(r < ZD ? Ws0[t] : 0.0f);
    }
    if (t < DIM * DIM) g_Ws1h[t] = __float2half(Ws1[t]);
    if (t < N_NODES) g_degS[t] = 0;
}

// ---------------- CSR build (by src), parallel scan ----------------
__global__ void k_count(const int* __restrict__ esrc) {
    int e = blockIdx.x * blockDim.x + threadIdx.x;
    if (e < N_EDGES) atomicAdd(&g_degS[esrc[e]], 1);
}
__global__ void k_scan1() {
    __shared__ int s[256];
    int t = threadIdx.x, idx = blockIdx.x * 256 + t;
    s[t] = (idx < N_NODES) ? g_degS[idx] : 0;
    __syncthreads();
    #pragma unroll
    for (int d = 128; d > 0; d >>= 1) {
        if (t < d) s[t] += s[t + d];
        __syncthreads();
    }
    if (t == 0) g_part[blockIdx.x] = s[0];
}
__global__ void k_scan2() {
    __shared__ int s[128];
    int t = threadIdx.x;
    int v = (t < SCAN_BLKS) ? g_part[t] : 0;
    s[t] = v;
    __syncthreads();
    #pragma unroll
    for (int d = 1; d < 128; d <<= 1) {
        int x = (t >= d) ? s[t - d] : 0;
        __syncthreads();
        s[t] += x;
        __syncthreads();
    }
    if (t < SCAN_BLKS) g_part[t] = s[t] - v;
    if (t == 127) g_offS[N_NODES] = s[127];
}
__global__ void k_scan3() {
    __shared__ int s[256];
    int t = threadIdx.x, idx = blockIdx.x * 256 + t;
    int v = (idx < N_NODES) ? g_degS[idx] : 0;
    s[t] = v;
    __syncthreads();
    #pragma unroll
    for (int d = 1; d < 256; d <<= 1) {
        int x = (t >= d) ? s[t - d] : 0;
        __syncthreads();
        s[t] += x;
        __syncthreads();
    }
    int excl = s[t] - v + g_part[blockIdx.x];
    if (idx < N_NODES) {
        g_offS[idx] = excl;
        g_curS[idx] = excl;
    }
}
__global__ void k_fillS(const int* __restrict__ esrc, const int* __restrict__ edst,
                        const float* __restrict__ dist, const float* __restrict__ sw) {
    int e = blockIdx.x * blockDim.x + threadIdx.x;
    if (e < N_EDGES) {
        int pos = atomicAdd(&g_curS[esrc[e]], 1);
        g_dstS[pos]  = edst[e];
        g_distS[pos] = dist[e];
        g_swS[pos]   = sw[e];
    }
}

// ---------------- edge aggregation: T[n] = sum_{e:src=n} s_e x z_dst ------
__global__ __launch_bounds__(256) void k_edgeT1() {
    const int warp = threadIdx.x >> 5;
    const int lane = threadIdx.x & 31;
    const int n = blockIdx.x * 8 + warp;
    if (n >= N_NODES) return;

    float acc[16][4];
    #pragma unroll
    for (int b = 0; b < 16; b++)
        #pragma unroll
        for (int i = 0; i < 4; i++) acc[b][i] = 0.0f;

    const int p0 = g_offS[n], p1 = g_offS[n + 1];
    const float sigma  = 0.8f / 15.0f;
    const float rsigma = 15.0f / 0.8f;
    const float mu_l   = 0.2f + (float)(lane & 15) * sigma;

    for (int p = p0; p < p1; p++) {
        const int dst = g_dstS[p];
        const float di = g_distS[p];
        const float sw = g_swS[p];
        float rinv = 1.0f / di;
        float x = (rinv - mu_l) * rsigma;
        float sv = __expf(-0.5f * x * x) * sw;

        float4 zv = *(const float4*)&g_zi[(size_t)dst * DIM + lane * 4];
        #pragma unroll
        for (int b = 0; b < 16; b++) {
            float sb = __shfl_sync(0xffffffffu, sv, b);
            acc[b][0] += sb * zv.x;
            acc[b][1] += sb * zv.y;
            acc[b][2] += sb * zv.z;
            acc[b][3] += sb * zv.w;
        }
    }

    __half* Ap = g_A + (size_t)n * KT1;
    #pragma unroll
    for (int b = 0; b < 16; b++) {
        __half2 h0 = __floats2half2_rn(acc[b][0], acc[b][1]);
        __half2 h1 = __floats2half2_rn(acc[b][2], acc[b][3]);
        uint2 st;
        st.x = *(unsigned*)&h0;
        st.y = *(unsigned*)&h1;
        *(uint2*)&Ap[b * DIM + lane * 4] = st;
    }
}

__global__ __launch_bounds__(256) void k_edgeT0() {
    const int warp = threadIdx.x >> 5;
    const int lane = threadIdx.x & 31;
    const int n = blockIdx.x * 8 + warp;
    if (n >= N_NODES) return;

    float acc[8];
    #pragma unroll
    for (int j = 0; j < 8; j++) acc[j] = 0.0f;

    const int p0 = g_offS[n], p1 = g_offS[n + 1];
    const int k  = lane & 15;
    const int bb = (lane >> 4) * 8;
    const float sigma  = 0.8f / 15.0f;
    const float rsigma = 15.0f / 0.8f;
    const float mu_l   = 0.2f + (float)k * sigma;

    for (int p = p0; p < p1; p++) {
        const int dst = g_dstS[p];
        const float di = g_distS[p];
        const float sw = g_swS[p];
        float rinv = 1.0f / di;
        float x = (rinv - mu_l) * rsigma;
        float sv = __expf(-0.5f * x * x) * sw;

        float zv = __half2float(g_z16h[dst * 32 + k]);
        #pragma unroll
        for (int j = 0; j < 8; j++) {
            float sb = __shfl_sync(0xffffffffu, sv, bb + j);
            acc[j] += sb * zv;
        }
    }

    __half* Ap = g_A + (size_t)n * KT0;
    #pragma unroll
    for (int j = 0; j < 8; j++)
        Ap[(bb + j) * ZD + k] = __float2half(acc[j]);
}

// ---------------- TC GEMM + fused zself + epilogue ------------------------
// zi = silu(T @ Vflat + z @ Ws + bs). K in {256,2048}, K2 in {32,128}.
#define CPA16(dst, src, bytes) \
    asm volatile("cp.async.cg.shared.global [%0], [%1], 16, %2;" \
                 :: "r"(dst), "l"(src), "r"(bytes))

__global__ __launch_bounds__(256, 2) void k_hgemmE(
    const __half* __restrict__ A, const __half* __restrict__ B,
    const __half* __restrict__ A2, const __half* __restrict__ W2,
    const float* __restrict__ bs, float* __restrict__ outz, int K, int K2)
{
    __shared__ __half As[2][128][40];
    __shared__ __half Bs[2][32][136];

    const int t    = threadIdx.x;
    const int warp = t >> 5, lane = t & 31;
    const int wm = (warp & 3) * 32;
    const int wn = (warp >> 2) * 64;
    const int m0 = blockIdx.x * 128;

    const int arow = t >> 1, ak = (t & 1) * 8;
    const int brow = t >> 4, bcol = (t & 15) * 8;
    const int gm = m0 + arow;
    const int apred = (gm < N_NODES) ? 16 : 0;
    const __half* Abase = &A[(size_t)gm * K];

    float acc[2][8][4];
    #pragma unroll
    for (int mt = 0; mt < 2; mt++)
        #pragma unroll
        for (int nt = 0; nt < 8; nt++)
            #pragma unroll
            for (int i = 0; i < 4; i++) acc[mt][nt][i] = 0.0f;

    const int T = K >> 5;

    {
        unsigned da0 = (unsigned)__cvta_generic_to_shared(&As[0][arow][ak]);
        unsigned da1 = (unsigned)__cvta_generic_to_shared(&As[0][arow][16 + ak]);
        CPA16(da0, Abase + ak, apred);
        CPA16(da1, Abase + 16 + ak, apred);
        unsigned db0 = (unsigned)__cvta_generic_to_shared(&Bs[0][brow][bcol]);
        unsigned db1 = (unsigned)__cvta_generic_to_shared(&Bs[0][16 + brow][bcol]);
        CPA16(db0, &B[(size_t)brow * DIM + bcol], 16);
        CPA16(db1, &B[(size_t)(16 + brow) * DIM + bcol], 16);
        asm volatile("cp.async.commit_group;");
    }

    for (int tt = 0; tt < T; tt++) {
        if (tt + 1 < T) {
            const int buf = (tt + 1) & 1, k0 = (tt + 1) * 32;
            unsigned da0 = (unsigned)__cvta_generic_to_shared(&As[buf][arow][ak]);
            unsigned da1 = (unsigned)__cvta_generic_to_shared(&As[buf][arow][16 + ak]);
            CPA16(da0, Abase + k0 + ak, apred);
            CPA16(da1, Abase + k0 + 16 + ak, apred);
            unsigned db0 = (unsigned)__cvta_generic_to_shared(&Bs[buf][brow][bcol]);
            unsigned db1 = (unsigned)__cvta_generic_to_shared(&Bs[buf][16 + brow][bcol]);
            CPA16(db0, &B[(size_t)(k0 + brow) * DIM + bcol], 16);
            CPA16(db1, &B[(size_t)(k0 + 16 + brow) * DIM + bcol], 16);
            asm volatile("cp.async.commit_group;");
            asm volatile("cp.async.wait_group 1;");
        } else {
            asm volatile("cp.async.wait_group 0;");
        }
        __syncthreads();

        const int buf = tt & 1;
        #pragma unroll
        for (int sub = 0; sub < 2; sub++) {
            const int kc = sub * 16;
            unsigned af[2][4];
            #pragma unroll
            for (int mt = 0; mt < 2; mt++) {
                const __half* p = &As[buf][wm + mt*16 + (lane & 15)][kc + ((lane >> 4) << 3)];
                unsigned addr = (unsigned)__cvta_generic_to_shared(p);
                asm volatile("ldmatrix.sync.aligned.m8n8.x4.shared.b16 {%0,%1,%2,%3}, [%4];"
                    : "=r"(af[mt][0]), "=r"(af[mt][1]), "=r"(af[mt][2]), "=r"(af[mt][3])
                    : "r"(addr));
            }
            unsigned bf[8][2];
            #pragma unroll
            for (int q = 0; q < 4; q++) {
                const __half* p = &Bs[buf][kc + (lane & 15)][wn + q*16 + ((lane >> 4) << 3)];
                unsigned addr = (unsigned)__cvta_generic_to_shared(p);
                asm volatile("ldmatrix.sync.aligned.m8n8.x4.trans.shared.b16 {%0,%1,%2,%3}, [%4];"
                    : "=r"(bf[q*2][0]), "=r"(bf[q*2][1]), "=r"(bf[q*2+1][0]), "=r"(bf[q*2+1][1])
                    : "r"(addr));
            }
            #pragma unroll
            for (int mt = 0; mt < 2; mt++)
                #pragma unroll
                for (int nt = 0; nt < 8; nt++) {
                    asm volatile(
                        "mma.sync.aligned.m16n8k16.row.col.f32.f16.f16.f32 "
                        "{%0,%1,%2,%3}, {%4,%5,%6,%7}, {%8,%9}, {%0,%1,%2,%3};"
                        : "+f"(acc[mt][nt][0]), "+f"(acc[mt][nt][1]),
                          "+f"(acc[mt][nt][2]), "+f"(acc[mt][nt][3])
                        : "r"(af[mt][0]), "r"(af[mt][1]), "r"(af[mt][2]), "r"(af[mt][3]),
                          "r"(bf[nt][0]), "r"(bf[nt][1]));
                }
        }
        __syncthreads();
    }

    // ---- second GEMM: z @ Ws, K2 tiles of 32, plain loads into buf 0 ----
    const int T2 = K2 >> 5;
    for (int q = 0; q < T2; q++) {
        // A2 tile: row arow, cols q*32 + (t&1)*16 + {0,8}
        uint4 a0 = make_uint4(0,0,0,0), a1 = a0;
        if (gm < N_NODES) {
            const __half* p = &A2[(size_t)gm * K2 + q*32 + (t & 1) * 16];
            a0 = *(const uint4*)p;
            a1 = *(const uint4*)(p + 8);
        }
        uint4 b0 = *(const uint4*)&W2[(size_t)(q*32 + brow) * DIM + bcol];
        uint4 b1 = *(const uint4*)&W2[(size_t)(q*32 + 16 + brow) * DIM + bcol];
        __syncthreads();
        *(uint4*)&As[0][arow][(t & 1) * 16]     = a0;
        *(uint4*)&As[0][arow][(t & 1) * 16 + 8] = a1;
        *(uint4*)&Bs[0][brow][bcol]      = b0;
        *(uint4*)&Bs[0][16 + brow][bcol] = b1;
        __syncthreads();

        #pragma unroll
        for (int sub = 0; sub < 2; sub++) {
            const int kc = sub * 16;
            unsigned af[2][4];
            #pragma unroll
            for (int mt = 0; mt < 2; mt++) {
                const __half* p = &As[0][wm + mt*16 + (lane & 15)][kc + ((lane >> 4) << 3)];
                unsigned addr = (unsigned)__cvta_generic_to_shared(p);
                asm volatile("ldmatrix.sync.aligned.m8n8.x4.shared.b16 {%0,%1,%2,%3}, [%4];"
                    : "=r"(af[mt][0]), "=r"(af[mt][1]), "=r"(af[mt][2]), "=r"(af[mt][3])
                    : "r"(addr));
            }
            unsigned bf[8][2];
            #pragma unroll
            for (int qq = 0; qq < 4; qq++) {
                const __half* p = &Bs[0][kc + (lane & 15)][wn + qq*16 + ((lane >> 4) << 3)];
                unsigned addr = (unsigned)__cvta_generic_to_shared(p);
                asm volatile("ldmatrix.sync.aligned.m8n8.x4.trans.shared.b16 {%0,%1,%2,%3}, [%4];"
                    : "=r"(bf[qq*2][0]), "=r"(bf[qq*2][1]), "=r"(bf[qq*2+1][0]), "=r"(bf[qq*2+1][1])
                    : "r"(addr));
            }
            #pragma unroll
            for (int mt = 0; mt < 2; mt++)
                #pragma unroll
                for (int nt = 0; nt < 8; nt++) {
                    asm volatile(
                        "mma.sync.aligned.m16n8k16.row.col.f32.f16.f16.f32 "
                        "{%0,%1,%2,%3}, {%4,%5,%6,%7}, {%8,%9}, {%0,%1,%2,%3};"
                        : "+f"(acc[mt][nt][0]), "+f"(acc[mt][nt][1]),
                          "+f"(acc[mt][nt][2]), "+f"(acc[mt][nt][3])
                        : "r"(af[mt][0]), "r"(af[mt][1]), "r"(af[mt][2]), "r"(af[mt][3]),
                          "r"(bf[nt][0]), "r"(bf[nt][1]));
                }
        }
        __syncthreads();
    }

    const int g = lane >> 2, t4 = lane & 3;
    #pragma unroll
    for (int mt = 0; mt < 2; mt++) {
        #pragma unroll
        for (int nt = 0; nt < 8; nt++) {
            int col = wn + nt*8 + 2*t4;
            float b0 = bs[col], b1 = bs[col + 1];
            #pragma unroll
            for (int h = 0; h < 2; h++) {
                int row = m0 + wm + mt*16 + g + h*8;
                if (row >= N_NODES) continue;
                float2 o;
                o.x = silu_f(acc[mt][nt][h*2 + 0] + b0);
                o.y = silu_f(acc[mt][nt][h*2 + 1] + b1);
                *(float2*)&outz[(size_t)row * DIM + col] = o;
            }
        }
    }
}

// ---------------- shared mma helper: 32x64 warp tile over K=128 in smem ---
__device__ __forceinline__ void mma_k128(
    const __half (*Amat)[136], const __half (*Bmat)[136],
    int wm, int wn, int lane, float acc[2][8][4])
{
    #pragma unroll
    for (int kc = 0; kc < 128; kc += 16) {
        unsigned af[2][4];
        #pragma unroll
        for (int mt = 0; mt < 2; mt++) {
            const __half* p = &Amat[wm + mt*16 + (lane & 15)][kc + ((lane >> 4) << 3)];
            unsigned addr = (unsigned)__cvta_generic_to_shared(p);
            asm volatile("ldmatrix.sync.aligned.m8n8.x4.shared.b16 {%0,%1,%2,%3}, [%4];"
                : "=r"(af[0][0]), "=r"(af[0][1]), "=r"(af[0][2]), "=r"(af[0][3])
                : "r"(addr));
            af[mt][0]=af[0][0]; af[mt][1]=af[0][1]; af[mt][2]=af[0][2]; af[mt][3]=af[0][3];
            if (mt == 0) {
                // placeholder to keep both fragments distinct; real loads below
            }
        }
        // (reload properly: two distinct ldmatrix calls)
        unsigned af0[4], af1[4];
        {
            const __half* p = &Amat[wm + 0 + (lane & 15)][kc + ((lane >> 4) << 3)];
            unsigned addr = (unsigned)__cvta_generic_to_shared(p);
            asm volatile("ldmatrix.sync.aligned.m8n8.x4.shared.b16 {%0,%1,%2,%3}, [%4];"
                : "=r"(af0[0]), "=r"(af0[1]), "=r"(af0[2]), "=r"(af0[3]) : "r"(addr));
        }
        {
            const __half* p = &Amat[wm + 16 + (lane & 15)][kc + ((lane >> 4) << 3)];
            unsigned addr = (unsigned)__cvta_generic_to_shared(p);
            asm volatile("ldmatrix.sync.aligned.m8n8.x4.shared.b16 {%0,%1,%2,%3}, [%4];"
                : "=r"(af1[0]), "=r"(af1[1]), "=r"(af1[2]), "=r"(af1[3]) : "r"(addr));
        }
        unsigned bf[8][2];
        #pragma unroll
        for (int q = 0; q < 4; q++) {
            const __half* p = &Bmat[kc + (lane & 15)][wn + q*16 + ((lane >> 4) << 3)];
            unsigned addr = (unsigned)__cvta_generic_to_shared(p);
            asm volatile("ldmatrix.sync.aligned.m8n8.x4.trans.shared.b16 {%0,%1,%2,%3}, [%4];"
                : "=r"(bf[q*2][0]), "=r"(bf[q*2][1]), "=r"(bf[q*2+1][0]), "=r"(bf[q*2+1][1])
                : "r"(addr));
        }
        #pragma unroll
        for (int nt = 0; nt < 8; nt++) {
            asm volatile(
                "mma.sync.aligned.m16n8k16.row.col.f32.f16.f16.f32 "
                "{%0,%1,%2,%3}, {%4,%5,%6,%7}, {%8,%9}, {%0,%1,%2,%3};"
                : "+f"(acc[0][nt][0]), "+f"(acc[0][nt][1]),
                  "+f"(acc[0][nt][2]), "+f"(acc[0][nt][3])
                : "r"(af0[0]), "r"(af0[1]), "r"(af0[2]), "r"(af0[3]),
                  "r"(bf[nt][0]), "r"(bf[nt][1]));
            asm volatile(
                "mma.sync.aligned.m16n8k16.row.col.f32.f16.f16.f32 "
                "{%0,%1,%2,%3}, {%4,%5,%6,%7}, {%8,%9}, {%0,%1,%2,%3};"
                : "+f"(acc[1][nt][0]), "+f"(acc[1][nt][1]),
                  "+f"(acc[1][nt][2]), "+f"(acc[1][nt][3])
                : "r"(af1[0]), "r"(af1[1]), "r"(af1[2]), "r"(af1[3]),
                  "r"(bf[nt][0]), "r"(bf[nt][1]));
        }
    }
}

// ---------------- fused 3x onsite: zi = A + silu(A@Wa+ba)@Wb + bb, x3 -----
// LAYER=0: writes zi (fp32), zih (fp16), out zis slot0.
// LAYER=1: writes out final + zis slot1.
template<int LAYER>
__global__ __launch_bounds__(256) void k_onsite3(
    const float* __restrict__ in, const __half* __restrict__ WaBase,
    const float* __restrict__ baBase, const __half* __restrict__ WbBase,
    const float* __restrict__ bbBase, float* __restrict__ zi_out,
    __half* __restrict__ zih_out, float* __restrict__ out)
{
    extern __shared__ char sm[];
    __half (*As)[136] = (__half(*)[136])sm;
    __half (*Ws)[136] = (__half(*)[136])(sm + 34816);
    float  (*R)[DIM]  = (float (*)[DIM])(sm + 69632);

    const int t = threadIdx.x;
    const int warp = t >> 5, lane = t & 31;
    const int wm = (warp & 3) * 32, wn = (warp >> 2) * 64;
    const int m0 = blockIdx.x * 128;
    const int r = t >> 1, c0 = (t & 1) * 64;
    const int gm = m0 + r;
    const int g4 = lane >> 2, t4 = lane & 3;

    #pragma unroll
    for (int i = 0; i < 16; i++) {
        float4 v = make_float4(0.f,0.f,0.f,0.f);
        if (gm < N_NODES) v = *(const float4*)&in[(size_t)gm * DIM + c0 + i*4];
        *(__half2*)&As[r][c0 + i*4]     = __floats2half2_rn(v.x, v.y);
        *(__half2*)&As[r][c0 + i*4 + 2] = __floats2half2_rn(v.z, v.w);
        *(float4*)&R[r][c0 + i*4] = v;
    }

    for (int j = 0; j < 3; j++) {
        const __half* Wa = WaBase + j * DIM * DIM;
        const __half* Wb = WbBase + j * DIM * DIM;
        const float*  ba = baBase + j * DIM;
        const float*  bb = bbBase + j * DIM;

        #pragma unroll
        for (int i = 0; i < 8; i++)
            *(uint4*)&Ws[r][c0 + i*8] = *(const uint4*)&Wa[r * DIM + c0 + i*8];
        __syncthreads();

        float acc[2][8][4];
        #pragma unroll
        for (int mt = 0; mt < 2; mt++)
            #pragma unroll
            for (int nt = 0; nt < 8; nt++)
                #pragma unroll
                for (int i = 0; i < 4; i++) acc[mt][nt][i] = 0.0f;

        mma_k128(As, Ws, wm, wn, lane, acc);
        __syncthreads();

        // H = silu(acc + ba) -> As; Wb -> Ws
        #pragma unroll
        for (int mt = 0; mt < 2; mt++) {
            #pragma unroll
            for (int nt = 0; nt < 8; nt++) {
                int col = wn + nt*8 + 2*t4;
                float b0 = ba[col], b1 = ba[col + 1];
                int r0 = wm + mt*16 + g4;
                *(__half2*)&As[r0][col] =
                    __floats2half2_rn(silu_f(acc[mt][nt][0] + b0), silu_f(acc[mt][nt][1] + b1));
                *(__half2*)&As[r0 + 8][col] =
                    __floats2half2_rn(silu_f(acc[mt][nt][2] + b0), silu_f(acc[mt][nt][3] + b1));
            }
        }
        #pragma unroll
        for (int i = 0; i < 8; i++)
            *(uint4*)&Ws[r][c0 + i*8] = *(const uint4*)&Wb[r * DIM + c0 + i*8];
        __syncthreads();

        #pragma unroll
        for (int mt = 0; mt < 2; mt++)
            #pragma unroll
            for (int nt = 0; nt < 8; nt++)
                #pragma unroll
                for (int i = 0; i < 4; i++) acc[mt][nt][i] = 0.0f;

        mma_k128(As, Ws, wm, wn, lane, acc);
        __syncthreads();

        // out = acc + bb + R
        #pragma unroll
        for (int mt = 0; mt < 2; mt++) {
            #pragma unroll
            for (int nt = 0; nt < 8; nt++) {
                int col = wn + nt*8 + 2*t4;
                float b0 = bb[col], b1 = bb[col + 1];
                #pragma unroll
                for (int h = 0; h < 2; h++) {
                    int rl = wm + mt*16 + g4 + h*8;
                    float2 o;
                    o.x = acc[mt][nt][h*2 + 0] + b0 + R[rl][col];
                    o.y = acc[mt][nt][h*2 + 1] + b1 + R[rl][col + 1];
                    if (j < 2) {
                        R[rl][col] = o.x; R[rl][col + 1] = o.y;
                        *(__half2*)&As[rl][col] = __floats2half2_rn(o.x, o.y);
                    } else {
                        int row = m0 + rl;
                        if (row < N_NODES) {
                            if (LAYER == 0) {
                                *(float2*)&zi_out[(size_t)row * DIM + col] = o;
                                *(__half2*)&zih_out[(size_t)row * DIM + col] =
                                    __floats2half2_rn(o.x, o.y);
                                *(float2*)&out[(size_t)N_NODES * DIM + (size_t)row * 2 * DIM + col] = o;
                            } else {
                                *(float2*)&out[(size_t)row * DIM + col] = o;
                                *(float2*)&out[(size_t)N_NODES * DIM + (size_t)row * 2 * DIM + DIM + col] = o;
                            }
                        }
                    }
                }
            }
        }
        __syncthreads();
    }
}

// ---------------- host driver ----------------
extern "C" void kernel_launch(void* const* d_in, const int* in_sizes, int n_in,
                              void* d_out, int out_size)
{
    const int*   species = (const int*)  d_in[0];
    const int*   esrc    = (const int*)  d_in[1];
    const int*   edst    = (const int*)  d_in[2];
    const float* dist    = (const float*)d_in[3];
    const float* swp     = (const float*)d_in[4];
    const float* Z       = (const float*)d_in[5];
    const float* Ws0     = (const float*)d_in[6];
    const float* bs0     = (const float*)d_in[7];
    const float* V0      = (const float*)d_in[8];
    const float* Ws1     = (const float*)d_in[9];
    const float* bs1     = (const float*)d_in[10];
    const float* V1      = (const float*)d_in[11];
    const float* Won_a   = (const float*)d_in[12];
    const float* bon_a   = (const float*)d_in[13];
    const float* Won_b   = (const float*)d_in[14];
    const float* bon_b   = (const float*)d_in[15];
    float* out = (float*)d_out;

    float *zi;
    __half *Ah, *Vh0, *Vh1, *z16h, *zih, *Ws0h, *Ws1h, *Wah, *Wbh;
    cudaGetSymbolAddress((void**)&zi,    g_zi);
    cudaGetSymbolAddress((void**)&Ah,    g_A);
    cudaGetSymbolAddress((void**)&Vh0,   g_Vh0);
    cudaGetSymbolAddress((void**)&Vh1,   g_Vh1);
    cudaGetSymbolAddress((void**)&z16h,  g_z16h);
    cudaGetSymbolAddress((void**)&zih,   g_zih);
    cudaGetSymbolAddress((void**)&Ws0h,  g_Ws0h);
    cudaGetSymbolAddress((void**)&Ws1h,  g_Ws1h);
    cudaGetSymbolAddress((void**)&Wah,   g_Wah);
    cudaGetSymbolAddress((void**)&Wbh,   g_Wbh);

    const int MB = (N_NODES + 127) / 128;       // 157
    const int EB = (N_EDGES + 255) / 256;
    const int NBK = (N_NODES + 7) / 8;
    const int PREP_N = N_NODES * 32;            // 640000, largest prep range

    const int ONSITE_SMEM = 34816 * 2 + 128 * DIM * 4;  // 135168
    static int attr_done = 0;
    if (!attr_done) {
        cudaFuncSetAttribute(k_onsite3<0>, cudaFuncAttributeMaxDynamicSharedMemorySize, ONSITE_SMEM);
        cudaFuncSetAttribute(k_onsite3<1>, cudaFuncAttributeMaxDynamicSharedMemorySize, ONSITE_SMEM);
        attr_done = 1;
    }

    // ---- preprocessing ----
    k_prep<<<(PREP_N + 255) / 256, 256>>>(species, Z, V0, V1, Ws0, Ws1, Won_a, Won_b);
    k_count<<<EB, 256>>>(esrc);
    k_scan1<<<SCAN_BLKS, 256>>>();
    k_scan2<<<1, 128>>>();
    k_scan3<<<SCAN_BLKS, 256>>>();
    k_fillS<<<EB, 256>>>(esrc, edst, dist, swp);

    // ---- layer 0 ----
    k_edgeT0<<<NBK, 256>>>();
    k_hgemmE<<<MB, 256>>>(Ah, Vh0, z16h, Ws0h, bs0, zi, KT0, 32);
    k_onsite3<0><<<MB, 256, ONSITE_SMEM>>>(zi,
        Wah + 0*3*DIM*DIM, bon_a + 0*3*DIM, Wbh + 0*3*DIM*DIM, bon_b + 0*3*DIM,
        zi, zih, out);

    // ---- layer 1 ----
    k_edgeT1<<<NBK, 256>>>();
    k_hgemmE<<<MB, 256>>>(Ah, Vh1, zih, Ws1h, bs1, zi, KT1, DIM);
    k_onsite3<1><<<MB, 256, ONSITE_SMEM>>>(zi,
        Wah + 1*3*DIM*DIM, bon_a + 1*3*DIM, Wbh + 1*3*DIM*DIM, bon_b + 1*3*DIM,
        zi, zih, out);
}

// round 9
// speedup vs baseline: 2.4027x; 1.1795x over previous
#include <cuda_runtime.h>
#include <cuda_fp16.h>
#include <math.h>

#define N_NODES 20000
#define N_EDGES 400000
#define DIM 128
#define NB 16
#define ZD 16
#define NLAYERS 2
#define KT1 (NB*DIM)   // 2048
#define KT0 (NB*ZD)    // 256
#define SCAN_BLKS ((N_NODES + 255) / 256)   // 79

// ---------------- device scratch (static, no allocations) ----------------
__device__ float  g_zi[N_NODES*DIM];
__device__ __half g_A[(size_t)N_NODES*KT1];     // aggregated T rows (fp16)
__device__ __half g_z16h[N_NODES*32];           // layer0 features, padded K2=32
__device__ __half g_zih[N_NODES*DIM];           // fp16 copy of layer0 output
__device__ __half g_Vh0[KT0*DIM];               // V0.reshape(-1,128) fp16
__device__ __half g_Vh1[KT1*DIM];               // V1.reshape(-1,128) fp16
__device__ __half g_Ws0h[32*DIM];               // Ws0 padded to 32 rows, fp16
__device__ __half g_Ws1h[DIM*DIM];              // Ws1 fp16
__device__ __half g_Wah[NLAYERS*3*DIM*DIM];     // onsite Wa fp16
__device__ __half g_Wbh[NLAYERS*3*DIM*DIM];     // onsite Wb fp16

// CSR by src + reordered edge data
__device__ int   g_degS[N_NODES], g_offS[N_NODES+1], g_curS[N_NODES];
__device__ int   g_part[128];
__device__ int   g_dstS[N_EDGES];
__device__ float g_distS[N_EDGES];
__device__ float g_swS[N_EDGES];

__device__ __forceinline__ float silu_f(float x) {
    return x / (1.0f + __expf(-x));
}

// ---------------- merged preprocessing ----------------
__global__ void k_prep(const int* __restrict__ species, const float* __restrict__ Z,
                       const float* __restrict__ V0, const float* __restrict__ V1,
                       const float* __restrict__ Ws0, const float* __restrict__ Ws1,
                       const float* __restrict__ Wa, const float* __restrict__ Wb)
{
    int t = blockIdx.x * blockDim.x + threadIdx.x;
    if (t < N_NODES * 32) {
        int n = t >> 5, c = t & 31;
        g_z16h[t] = __float2half(c < ZD ? Z[species[n] * ZD + c] : 0.0f);
    }
    if (t < KT1 * DIM) g_Vh1[t] = __float2half(V1[t]);
    if (t < KT0 * DIM) g_Vh0[t] = __float2half(V0[t]);
    if (t < NLAYERS * 3 * DIM * DIM) {
        g_Wah[t] = __float2half(Wa[t]);
        g_Wbh[t] = __float2half(Wb[t]);
    }
    if (t < 32 * DIM) {
        int r = t >> 7;
        g_Ws0h[t] = __float2half(r < ZD ? Ws0[t] : 0.0f);
    }
    if (t < DIM * DIM) g_Ws1h[t] = __float2half(Ws1[t]);
    if (t < N_NODES) g_degS[t] = 0;
}

// ---------------- CSR build (by src), parallel scan ----------------
__global__ void k_count(const int* __restrict__ esrc) {
    int e = blockIdx.x * blockDim.x + threadIdx.x;
    if (e < N_EDGES) atomicAdd(&g_degS[esrc[e]], 1);
}
__global__ void k_scan1() {
    __shared__ int s[256];
    int t = threadIdx.x, idx = blockIdx.x * 256 + t;
    s[t] = (idx < N_NODES) ? g_degS[idx] : 0;
    __syncthreads();
    #pragma unroll
    for (int d = 128; d > 0; d >>= 1) {
        if (t < d) s[t] += s[t + d];
        __syncthreads();
    }
    if (t == 0) g_part[blockIdx.x] = s[0];
}
__global__ void k_scan2() {
    __shared__ int s[128];
    int t = threadIdx.x;
    int v = (t < SCAN_BLKS) ? g_part[t] : 0;
    s[t] = v;
    __syncthreads();
    #pragma unroll
    for (int d = 1; d < 128; d <<= 1) {
        int x = (t >= d) ? s[t - d] : 0;
        __syncthreads();
        s[t] += x;
        __syncthreads();
    }
    if (t < SCAN_BLKS) g_part[t] = s[t] - v;
    if (t == 127) g_offS[N_NODES] = s[127];
}
__global__ void k_scan3() {
    __shared__ int s[256];
    int t = threadIdx.x, idx = blockIdx.x * 256 + t;
    int v = (idx < N_NODES) ? g_degS[idx] : 0;
    s[t] = v;
    __syncthreads();
    #pragma unroll
    for (int d = 1; d < 256; d <<= 1) {
        int x = (t >= d) ? s[t - d] : 0;
        __syncthreads();
        s[t] += x;
        __syncthreads();
    }
    int excl = s[t] - v + g_part[blockIdx.x];
    if (idx < N_NODES) {
        g_offS[idx] = excl;
        g_curS[idx] = excl;
    }
}
__global__ void k_fillS(const int* __restrict__ esrc, const int* __restrict__ edst,
                        const float* __restrict__ dist, const float* __restrict__ sw) {
    int e = blockIdx.x * blockDim.x + threadIdx.x;
    if (e < N_EDGES) {
        int pos = atomicAdd(&g_curS[esrc[e]], 1);
        g_dstS[pos]  = edst[e];
        g_distS[pos] = dist[e];
        g_swS[pos]   = sw[e];
    }
}

// ---------------- edge aggregation via tensor cores -----------------------
// T[n] (16 x DIM) = S^T (16 x deg) @ Z (deg x DIM), chunked K=16 per mma set.
// Warp per node; s and z tiles staged fp16 in smem, fp32 accumulators.
__global__ __launch_bounds__(256) void k_edgeT1() {
    __shared__ __half SA[8][16][24];    // [warp][basis][edge-slot]
    __shared__ __half SB[8][16][136];   // [warp][edge-slot][dim]

    const int warp = threadIdx.x >> 5;
    const int lane = threadIdx.x & 31;
    const int n = blockIdx.x * 8 + warp;
    if (n >= N_NODES) return;
    const int p0 = g_offS[n], p1 = g_offS[n + 1];

    float acc[16][4];
    #pragma unroll
    for (int nt = 0; nt < 16; nt++)
        #pragma unroll
        for (int i = 0; i < 4; i++) acc[nt][i] = 0.0f;

    const int el = lane & 15, hi = lane >> 4;
    const float sigma  = 0.8f / 15.0f;
    const float rsigma = 15.0f / 0.8f;

    for (int c = p0; c < p1; c += 16) {
        const int p = c + el;
        const bool v = (p < p1);
        const int dst   = v ? g_dstS[p]  : 0;
        const float di  = v ? g_distS[p] : 1.0f;
        const float sw  = v ? g_swS[p]   : 0.0f;
        const float rinv = 1.0f / di;

        // s tile: lane fills 8 bases for its edge slot
        #pragma unroll
        for (int j = 0; j < 8; j++) {
            const float mu = 0.2f + (float)(hi * 8 + j) * sigma;
            const float x = (rinv - mu) * rsigma;
            SA[warp][hi * 8 + j][el] = __float2half(__expf(-0.5f * x * x) * sw);
        }
        // z tile: gather 16 rows of 256B from fp16 zih (2 rows per round)
        #pragma unroll
        for (int r2 = 0; r2 < 8; r2++) {
            const int row = r2 * 2 + hi;
            const int rdst = __shfl_sync(0xffffffffu, dst, row);
            *(uint4*)&SB[warp][row][el * 8] =
                *(const uint4*)&g_zih[(size_t)rdst * DIM + el * 8];
        }
        __syncwarp();

        unsigned af[4];
        {
            const __half* pA = &SA[warp][el][hi * 8];
            unsigned addr = (unsigned)__cvta_generic_to_shared(pA);
            asm volatile("ldmatrix.sync.aligned.m8n8.x4.shared.b16 {%0,%1,%2,%3}, [%4];"
                : "=r"(af[0]), "=r"(af[1]), "=r"(af[2]), "=r"(af[3]) : "r"(addr));
        }
        #pragma unroll
        for (int q = 0; q < 8; q++) {
            unsigned bf[2][2];
            const __half* pB = &SB[warp][el][q * 16 + hi * 8];
            unsigned addr = (unsigned)__cvta_generic_to_shared(pB);
            asm volatile("ldmatrix.sync.aligned.m8n8.x4.trans.shared.b16 {%0,%1,%2,%3}, [%4];"
                : "=r"(bf[0][0]), "=r"(bf[0][1]), "=r"(bf[1][0]), "=r"(bf[1][1])
                : "r"(addr));
            #pragma unroll
            for (int h = 0; h < 2; h++) {
                asm volatile(
                    "mma.sync.aligned.m16n8k16.row.col.f32.f16.f16.f32 "
                    "{%0,%1,%2,%3}, {%4,%5,%6,%7}, {%8,%9}, {%0,%1,%2,%3};"
                    : "+f"(acc[q*2+h][0]), "+f"(acc[q*2+h][1]),
                      "+f"(acc[q*2+h][2]), "+f"(acc[q*2+h][3])
                    : "r"(af[0]), "r"(af[1]), "r"(af[2]), "r"(af[3]),
                      "r"(bf[h][0]), "r"(bf[h][1]));
            }
        }
        __syncwarp();
    }

    // store: C row = basis (g4, g4+8), col = dim
    const int g4 = lane >> 2, t4 = lane & 3;
    __half* Ap = g_A + (size_t)n * KT1;
    #pragma unroll
    for (int nt = 0; nt < 16; nt++) {
        *(__half2*)&Ap[(size_t)g4 * DIM + nt*8 + 2*t4] =
            __floats2half2_rn(acc[nt][0], acc[nt][1]);
        *(__half2*)&Ap[(size_t)(g4 + 8) * DIM + nt*8 + 2*t4] =
            __floats2half2_rn(acc[nt][2], acc[nt][3]);
    }
}

__global__ __launch_bounds__(256) void k_edgeT0() {
    __shared__ __half SA[8][16][24];    // [warp][basis][edge-slot]
    __shared__ __half SB[8][16][24];    // [warp][edge-slot][zdim]

    const int warp = threadIdx.x >> 5;
    const int lane = threadIdx.x & 31;
    const int n = blockIdx.x * 8 + warp;
    if (n >= N_NODES) return;
    const int p0 = g_offS[n], p1 = g_offS[n + 1];

    float acc[2][4];
    #pragma unroll
    for (int nt = 0; nt < 2; nt++)
        #pragma unroll
        for (int i = 0; i < 4; i++) acc[nt][i] = 0.0f;

    const int el = lane & 15, hi = lane >> 4;
    const float sigma  = 0.8f / 15.0f;
    const float rsigma = 15.0f / 0.8f;

    for (int c = p0; c < p1; c += 16) {
        const int p = c + el;
        const bool v = (p < p1);
        const int dst   = v ? g_dstS[p]  : 0;
        const float di  = v ? g_distS[p] : 1.0f;
        const float sw  = v ? g_swS[p]   : 0.0f;
        const float rinv = 1.0f / di;

        #pragma unroll
        for (int j = 0; j < 8; j++) {
            const float mu = 0.2f + (float)(hi * 8 + j) * sigma;
            const float x = (rinv - mu) * rsigma;
            SA[warp][hi * 8 + j][el] = __float2half(__expf(-0.5f * x * x) * sw);
        }
        // z tile: 16 rows x 16 halves; each lane loads one uint4 (8 halves)
        {
            const int row = lane >> 1;
            const int rdst = __shfl_sync(0xffffffffu, dst, row);
            *(uint4*)&SB[warp][row][(lane & 1) * 8] =
                *(const uint4*)&g_z16h[rdst * 32 + (lane & 1) * 8];
        }
        __syncwarp();

        unsigned af[4];
        {
            const __half* pA = &SA[warp][el][hi * 8];
            unsigned addr = (unsigned)__cvta_generic_to_shared(pA);
            asm volatile("ldmatrix.sync.aligned.m8n8.x4.shared.b16 {%0,%1,%2,%3}, [%4];"
                : "=r"(af[0]), "=r"(af[1]), "=r"(af[2]), "=r"(af[3]) : "r"(addr));
        }
        unsigned bf[2][2];
        {
            const __half* pB = &SB[warp][el][hi * 8];
            unsigned addr = (unsigned)__cvta_generic_to_shared(pB);
            asm volatile("ldmatrix.sync.aligned.m8n8.x4.trans.shared.b16 {%0,%1,%2,%3}, [%4];"
                : "=r"(bf[0][0]), "=r"(bf[0][1]), "=r"(bf[1][0]), "=r"(bf[1][1])
                : "r"(addr));
        }
        #pragma unroll
        for (int h = 0; h < 2; h++) {
            asm volatile(
                "mma.sync.aligned.m16n8k16.row.col.f32.f16.f16.f32 "
                "{%0,%1,%2,%3}, {%4,%5,%6,%7}, {%8,%9}, {%0,%1,%2,%3};"
                : "+f"(acc[h][0]), "+f"(acc[h][1]), "+f"(acc[h][2]), "+f"(acc[h][3])
                : "r"(af[0]), "r"(af[1]), "r"(af[2]), "r"(af[3]),
                  "r"(bf[h][0]), "r"(bf[h][1]));
        }
        __syncwarp();
    }

    const int g4 = lane >> 2, t4 = lane & 3;
    __half* Ap = g_A + (size_t)n * KT0;
    #pragma unroll
    for (int nt = 0; nt < 2; nt++) {
        *(__half2*)&Ap[g4 * ZD + nt*8 + 2*t4] =
            __floats2half2_rn(acc[nt][0], acc[nt][1]);
        *(__half2*)&Ap[(g4 + 8) * ZD + nt*8 + 2*t4] =
            __floats2half2_rn(acc[nt][2], acc[nt][3]);
    }
}

// ---------------- TC GEMM + fused zself + epilogue ------------------------
// zi = silu(T @ Vflat + z @ Ws + bs). K in {256,2048}, K2 in {32,128}.
#define CPA16(dst, src, bytes) \
    asm volatile("cp.async.cg.shared.global [%0], [%1], 16, %2;" \
                 :: "r"(dst), "l"(src), "r"(bytes))

__global__ __launch_bounds__(256, 2) void k_hgemmE(
    const __half* __restrict__ A, const __half* __restrict__ B,
    const __half* __restrict__ A2, const __half* __restrict__ W2,
    const float* __restrict__ bs, float* __restrict__ outz, int K, int K2)
{
    __shared__ __half As[2][128][40];
    __shared__ __half Bs[2][32][136];

    const int t    = threadIdx.x;
    const int warp = t >> 5, lane = t & 31;
    const int wm = (warp & 3) * 32;
    const int wn = (warp >> 2) * 64;
    const int m0 = blockIdx.x * 128;

    const int arow = t >> 1, ak = (t & 1) * 8;
    const int brow = t >> 4, bcol = (t & 15) * 8;
    const int gm = m0 + arow;
    const int apred = (gm < N_NODES) ? 16 : 0;
    const __half* Abase = &A[(size_t)gm * K];

    float acc[2][8][4];
    #pragma unroll
    for (int mt = 0; mt < 2; mt++)
        #pragma unroll
        for (int nt = 0; nt < 8; nt++)
            #pragma unroll
            for (int i = 0; i < 4; i++) acc[mt][nt][i] = 0.0f;

    const int T = K >> 5;

    {
        unsigned da0 = (unsigned)__cvta_generic_to_shared(&As[0][arow][ak]);
        unsigned da1 = (unsigned)__cvta_generic_to_shared(&As[0][arow][16 + ak]);
        CPA16(da0, Abase + ak, apred);
        CPA16(da1, Abase + 16 + ak, apred);
        unsigned db0 = (unsigned)__cvta_generic_to_shared(&Bs[0][brow][bcol]);
        unsigned db1 = (unsigned)__cvta_generic_to_shared(&Bs[0][16 + brow][bcol]);
        CPA16(db0, &B[(size_t)brow * DIM + bcol], 16);
        CPA16(db1, &B[(size_t)(16 + brow) * DIM + bcol], 16);
        asm volatile("cp.async.commit_group;");
    }

    for (int tt = 0; tt < T; tt++) {
        if (tt + 1 < T) {
            const int buf = (tt + 1) & 1, k0 = (tt + 1) * 32;
            unsigned da0 = (unsigned)__cvta_generic_to_shared(&As[buf][arow][ak]);
            unsigned da1 = (unsigned)__cvta_generic_to_shared(&As[buf][arow][16 + ak]);
            CPA16(da0, Abase + k0 + ak, apred);
            CPA16(da1, Abase + k0 + 16 + ak, apred);
            unsigned db0 = (unsigned)__cvta_generic_to_shared(&Bs[buf][brow][bcol]);
            unsigned db1 = (unsigned)__cvta_generic_to_shared(&Bs[buf][16 + brow][bcol]);
            CPA16(db0, &B[(size_t)(k0 + brow) * DIM + bcol], 16);
            CPA16(db1, &B[(size_t)(k0 + 16 + brow) * DIM + bcol], 16);
            asm volatile("cp.async.commit_group;");
            asm volatile("cp.async.wait_group 1;");
        } else {
            asm volatile("cp.async.wait_group 0;");
        }
        __syncthreads();

        const int buf = tt & 1;
        #pragma unroll
        for (int sub = 0; sub < 2; sub++) {
            const int kc = sub * 16;
            unsigned af[2][4];
            #pragma unroll
            for (int mt = 0; mt < 2; mt++) {
                const __half* p = &As[buf][wm + mt*16 + (lane & 15)][kc + ((lane >> 4) << 3)];
                unsigned addr = (unsigned)__cvta_generic_to_shared(p);
                asm volatile("ldmatrix.sync.aligned.m8n8.x4.shared.b16 {%0,%1,%2,%3}, [%4];"
                    : "=r"(af[mt][0]), "=r"(af[mt][1]), "=r"(af[mt][2]), "=r"(af[mt][3])
                    : "r"(addr));
            }
            unsigned bf[8][2];
            #pragma unroll
            for (int q = 0; q < 4; q++) {
                const __half* p = &Bs[buf][kc + (lane & 15)][wn + q*16 + ((lane >> 4) << 3)];
                unsigned addr = (unsigned)__cvta_generic_to_shared(p);
                asm volatile("ldmatrix.sync.aligned.m8n8.x4.trans.shared.b16 {%0,%1,%2,%3}, [%4];"
                    : "=r"(bf[q*2][0]), "=r"(bf[q*2][1]), "=r"(bf[q*2+1][0]), "=r"(bf[q*2+1][1])
                    : "r"(addr));
            }
            #pragma unroll
            for (int mt = 0; mt < 2; mt++)
                #pragma unroll
                for (int nt = 0; nt < 8; nt++) {
                    asm volatile(
                        "mma.sync.aligned.m16n8k16.row.col.f32.f16.f16.f32 "
                        "{%0,%1,%2,%3}, {%4,%5,%6,%7}, {%8,%9}, {%0,%1,%2,%3};"
                        : "+f"(acc[mt][nt][0]), "+f"(acc[mt][nt][1]),
                          "+f"(acc[mt][nt][2]), "+f"(acc[mt][nt][3])
                        : "r"(af[mt][0]), "r"(af[mt][1]), "r"(af[mt][2]), "r"(af[mt][3]),
                          "r"(bf[nt][0]), "r"(bf[nt][1]));
                }
        }
        __syncthreads();
    }

    // ---- second GEMM: z @ Ws, K2 tiles of 32, plain loads into buf 0 ----
    const int T2 = K2 >> 5;
    for (int q = 0; q < T2; q++) {
        uint4 a0 = make_uint4(0,0,0,0), a1 = a0;
        if (gm < N_NODES) {
            const __half* p = &A2[(size_t)gm * K2 + q*32 + (t & 1) * 16];
            a0 = *(const uint4*)p;
            a1 = *(const uint4*)(p + 8);
        }
        uint4 b0 = *(const uint4*)&W2[(size_t)(q*32 + brow) * DIM + bcol];
        uint4 b1 = *(const uint4*)&W2[(size_t)(q*32 + 16 + brow) * DIM + bcol];
        __syncthreads();
        *(uint4*)&As[0][arow][(t & 1) * 16]     = a0;
        *(uint4*)&As[0][arow][(t & 1) * 16 + 8] = a1;
        *(uint4*)&Bs[0][brow][bcol]      = b0;
        *(uint4*)&Bs[0][16 + brow][bcol] = b1;
        __syncthreads();

        #pragma unroll
        for (int sub = 0; sub < 2; sub++) {
            const int kc = sub * 16;
            unsigned af[2][4];
            #pragma unroll
            for (int mt = 0; mt < 2; mt++) {
                const __half* p = &As[0][wm + mt*16 + (lane & 15)][kc + ((lane >> 4) << 3)];
                unsigned addr = (unsigned)__cvta_generic_to_shared(p);
                asm volatile("ldmatrix.sync.aligned.m8n8.x4.shared.b16 {%0,%1,%2,%3}, [%4];"
                    : "=r"(af[mt][0]), "=r"(af[mt][1]), "=r"(af[mt][2]), "=r"(af[mt][3])
                    : "r"(addr));
            }
            unsigned bf[8][2];
            #pragma unroll
            for (int qq = 0; qq < 4; qq++) {
                const __half* p = &Bs[0][kc + (lane & 15)][wn + qq*16 + ((lane >> 4) << 3)];
                unsigned addr = (unsigned)__cvta_generic_to_shared(p);
                asm volatile("ldmatrix.sync.aligned.m8n8.x4.trans.shared.b16 {%0,%1,%2,%3}, [%4];"
                    : "=r"(bf[qq*2][0]), "=r"(bf[qq*2][1]), "=r"(bf[qq*2+1][0]), "=r"(bf[qq*2+1][1])
                    : "r"(addr));
            }
            #pragma unroll
            for (int mt = 0; mt < 2; mt++)
                #pragma unroll
                for (int nt = 0; nt < 8; nt++) {
                    asm volatile(
                        "mma.sync.aligned.m16n8k16.row.col.f32.f16.f16.f32 "
                        "{%0,%1,%2,%3}, {%4,%5,%6,%7}, {%8,%9}, {%0,%1,%2,%3};"
                        : "+f"(acc[mt][nt][0]), "+f"(acc[mt][nt][1]),
                          "+f"(acc[mt][nt][2]), "+f"(acc[mt][nt][3])
                        : "r"(af[mt][0]), "r"(af[mt][1]), "r"(af[mt][2]), "r"(af[mt][3]),
                          "r"(bf[nt][0]), "r"(bf[nt][1]));
                }
        }
        __syncthreads();
    }

    const int g = lane >> 2, t4 = lane & 3;
    #pragma unroll
    for (int mt = 0; mt < 2; mt++) {
        #pragma unroll
        for (int nt = 0; nt < 8; nt++) {
            int col = wn + nt*8 + 2*t4;
            float b0 = bs[col], b1 = bs[col + 1];
            #pragma unroll
            for (int h = 0; h < 2; h++) {
                int row = m0 + wm + mt*16 + g + h*8;
                if (row >= N_NODES) continue;
                float2 o;
                o.x = silu_f(acc[mt][nt][h*2 + 0] + b0);
                o.y = silu_f(acc[mt][nt][h*2 + 1] + b1);
                *(float2*)&outz[(size_t)row * DIM + col] = o;
            }
        }
    }
}

// ---------------- shared mma helper: 32x64 warp tile over K=128 in smem ---
__device__ __forceinline__ void mma_k128(
    const __half (*Amat)[136], const __half (*Bmat)[136],
    int wm, int wn, int lane, float acc[2][8][4])
{
    #pragma unroll
    for (int kc = 0; kc < 128; kc += 16) {
        unsigned af[2][4];
        #pragma unroll
        for (int mt = 0; mt < 2; mt++) {
            const __half* p = &Amat[wm + mt*16 + (lane & 15)][kc + ((lane >> 4) << 3)];
            unsigned addr = (unsigned)__cvta_generic_to_shared(p);
            asm volatile("ldmatrix.sync.aligned.m8n8.x4.shared.b16 {%0,%1,%2,%3}, [%4];"
                : "=r"(af[mt][0]), "=r"(af[mt][1]), "=r"(af[mt][2]), "=r"(af[mt][3])
                : "r"(addr));
        }
        unsigned bf[8][2];
        #pragma unroll
        for (int q = 0; q < 4; q++) {
            const __half* p = &Bmat[kc + (lane & 15)][wn + q*16 + ((lane >> 4) << 3)];
            unsigned addr = (unsigned)__cvta_generic_to_shared(p);
            asm volatile("ldmatrix.sync.aligned.m8n8.x4.trans.shared.b16 {%0,%1,%2,%3}, [%4];"
                : "=r"(bf[q*2][0]), "=r"(bf[q*2][1]), "=r"(bf[q*2+1][0]), "=r"(bf[q*2+1][1])
                : "r"(addr));
        }
        #pragma unroll
        for (int mt = 0; mt < 2; mt++)
            #pragma unroll
            for (int nt = 0; nt < 8; nt++) {
                asm volatile(
                    "mma.sync.aligned.m16n8k16.row.col.f32.f16.f16.f32 "
                    "{%0,%1,%2,%3}, {%4,%5,%6,%7}, {%8,%9}, {%0,%1,%2,%3};"
                    : "+f"(acc[mt][nt][0]), "+f"(acc[mt][nt][1]),
                      "+f"(acc[mt][nt][2]), "+f"(acc[mt][nt][3])
                    : "r"(af[mt][0]), "r"(af[mt][1]), "r"(af[mt][2]), "r"(af[mt][3]),
                      "r"(bf[nt][0]), "r"(bf[nt][1]));
            }
    }
}

// ---------------- fused 3x onsite: zi = A + silu(A@Wa+ba)@Wb + bb, x3 -----
// LAYER=0: writes zi (fp32), zih (fp16), out zis slot0.
// LAYER=1: writes out final + zis slot1.
template<int LAYER>
__global__ __launch_bounds__(256) void k_onsite3(
    const float* __restrict__ in, const __half* __restrict__ WaBase,
    const float* __restrict__ baBase, const __half* __restrict__ WbBase,
    const float* __restrict__ bbBase, float* __restrict__ zi_out,
    __half* __restrict__ zih_out, float* __restrict__ out)
{
    extern __shared__ char sm[];
    __half (*As)[136] = (__half(*)[136])sm;
    __half (*Ws)[136] = (__half(*)[136])(sm + 34816);
    float  (*R)[DIM]  = (float (*)[DIM])(sm + 69632);

    const int t = threadIdx.x;
    const int warp = t >> 5, lane = t & 31;
    const int wm = (warp & 3) * 32, wn = (warp >> 2) * 64;
    const int m0 = blockIdx.x * 128;
    const int r = t >> 1, c0 = (t & 1) * 64;
    const int gm = m0 + r;
    const int g4 = lane >> 2, t4 = lane & 3;

    #pragma unroll
    for (int i = 0; i < 16; i++) {
        float4 v = make_float4(0.f,0.f,0.f,0.f);
        if (gm < N_NODES) v = *(const float4*)&in[(size_t)gm * DIM + c0 + i*4];
        *(__half2*)&As[r][c0 + i*4]     = __floats2half2_rn(v.x, v.y);
        *(__half2*)&As[r][c0 + i*4 + 2] = __floats2half2_rn(v.z, v.w);
        *(float4*)&R[r][c0 + i*4] = v;
    }

    for (int j = 0; j < 3; j++) {
        const __half* Wa = WaBase + j * DIM * DIM;
        const __half* Wb = WbBase + j * DIM * DIM;
        const float*  ba = baBase + j * DIM;
        const float*  bb = bbBase + j * DIM;

        #pragma unroll
        for (int i = 0; i < 8; i++)
            *(uint4*)&Ws[r][c0 + i*8] = *(const uint4*)&Wa[r * DIM + c0 + i*8];
        __syncthreads();

        float acc[2][8][4];
        #pragma unroll
        for (int mt = 0; mt < 2; mt++)
            #pragma unroll
            for (int nt = 0; nt < 8; nt++)
                #pragma unroll
                for (int i = 0; i < 4; i++) acc[mt][nt][i] = 0.0f;

        mma_k128(As, Ws, wm, wn, lane, acc);
        __syncthreads();

        // H = silu(acc + ba) -> As; Wb -> Ws
        #pragma unroll
        for (int mt = 0; mt < 2; mt++) {
            #pragma unroll
            for (int nt = 0; nt < 8; nt++) {
                int col = wn + nt*8 + 2*t4;
                float b0 = ba[col], b1 = ba[col + 1];
                int r0 = wm + mt*16 + g4;
                *(__half2*)&As[r0][col] =
                    __floats2half2_rn(silu_f(acc[mt][nt][0] + b0), silu_f(acc[mt][nt][1] + b1));
                *(__half2*)&As[r0 + 8][col] =
                    __floats2half2_rn(silu_f(acc[mt][nt][2] + b0), silu_f(acc[mt][nt][3] + b1));
            }
        }
        #pragma unroll
        for (int i = 0; i < 8; i++)
            *(uint4*)&Ws[r][c0 + i*8] = *(const uint4*)&Wb[r * DIM + c0 + i*8];
        __syncthreads();

        #pragma unroll
        for (int mt = 0; mt < 2; mt++)
            #pragma unroll
            for (int nt = 0; nt < 8; nt++)
                #pragma unroll
                for (int i = 0; i < 4; i++) acc[mt][nt][i] = 0.0f;

        mma_k128(As, Ws, wm, wn, lane, acc);
        __syncthreads();

        // out = acc + bb + R
        #pragma unroll
        for (int mt = 0; mt < 2; mt++) {
            #pragma unroll
            for (int nt = 0; nt < 8; nt++) {
                int col = wn + nt*8 + 2*t4;
                float b0 = bb[col], b1 = bb[col + 1];
                #pragma unroll
                for (int h = 0; h < 2; h++) {
                    int rl = wm + mt*16 + g4 + h*8;
                    float2 o;
                    o.x = acc[mt][nt][h*2 + 0] + b0 + R[rl][col];
                    o.y = acc[mt][nt][h*2 + 1] + b1 + R[rl][col + 1];
                    if (j < 2) {
                        R[rl][col] = o.x; R[rl][col + 1] = o.y;
                        *(__half2*)&As[rl][col] = __floats2half2_rn(o.x, o.y);
                    } else {
                        int row = m0 + rl;
                        if (row < N_NODES) {
                            if (LAYER == 0) {
                                *(float2*)&zi_out[(size_t)row * DIM + col] = o;
                                *(__half2*)&zih_out[(size_t)row * DIM + col] =
                                    __floats2half2_rn(o.x, o.y);
                                *(float2*)&out[(size_t)N_NODES * DIM + (size_t)row * 2 * DIM + col] = o;
                            } else {
                                *(float2*)&out[(size_t)row * DIM + col] = o;
                                *(float2*)&out[(size_t)N_NODES * DIM + (size_t)row * 2 * DIM + DIM + col] = o;
                            }
                        }
                    }
                }
            }
        }
        __syncthreads();
    }
}

// ---------------- host driver ----------------
extern "C" void kernel_launch(void* const* d_in, const int* in_sizes, int n_in,
                              void* d_out, int out_size)
{
    const int*   species = (const int*)  d_in[0];
    const int*   esrc    = (const int*)  d_in[1];
    const int*   edst    = (const int*)  d_in[2];
    const float* dist    = (const float*)d_in[3];
    const float* swp     = (const float*)d_in[4];
    const float* Z       = (const float*)d_in[5];
    const float* Ws0     = (const float*)d_in[6];
    const float* bs0     = (const float*)d_in[7];
    const float* V0      = (const float*)d_in[8];
    const float* Ws1     = (const float*)d_in[9];
    const float* bs1     = (const float*)d_in[10];
    const float* V1      = (const float*)d_in[11];
    const float* Won_a   = (const float*)d_in[12];
    const float* bon_a   = (const float*)d_in[13];
    const float* Won_b   = (const float*)d_in[14];
    const float* bon_b   = (const float*)d_in[15];
    float* out = (float*)d_out;

    float *zi;
    __half *Ah, *Vh0, *Vh1, *z16h, *zih, *Ws0h, *Ws1h, *Wah, *Wbh;
    cudaGetSymbolAddress((void**)&zi,    g_zi);
    cudaGetSymbolAddress((void**)&Ah,    g_A);
    cudaGetSymbolAddress((void**)&Vh0,   g_Vh0);
    cudaGetSymbolAddress((void**)&Vh1,   g_Vh1);
    cudaGetSymbolAddress((void**)&z16h,  g_z16h);
    cudaGetSymbolAddress((void**)&zih,   g_zih);
    cudaGetSymbolAddress((void**)&Ws0h,  g_Ws0h);
    cudaGetSymbolAddress((void**)&Ws1h,  g_Ws1h);
    cudaGetSymbolAddress((void**)&Wah,   g_Wah);
    cudaGetSymbolAddress((void**)&Wbh,   g_Wbh);

    const int MB = (N_NODES + 127) / 128;       // 157
    const int EB = (N_EDGES + 255) / 256;
    const int NBK = (N_NODES + 7) / 8;
    const int PREP_N = N_NODES * 32;            // 640000, largest prep range

    const int ONSITE_SMEM = 34816 * 2 + 128 * DIM * 4;  // 135168
    static int attr_done = 0;
    if (!attr_done) {
        cudaFuncSetAttribute(k_onsite3<0>, cudaFuncAttributeMaxDynamicSharedMemorySize, ONSITE_SMEM);
        cudaFuncSetAttribute(k_onsite3<1>, cudaFuncAttributeMaxDynamicSharedMemorySize, ONSITE_SMEM);
        attr_done = 1;
    }

    // ---- preprocessing ----
    k_prep<<<(PREP_N + 255) / 256, 256>>>(species, Z, V0, V1, Ws0, Ws1, Won_a, Won_b);
    k_count<<<EB, 256>>>(esrc);
    k_scan1<<<SCAN_BLKS, 256>>>();
    k_scan2<<<1, 128>>>();
    k_scan3<<<SCAN_BLKS, 256>>>();
    k_fillS<<<EB, 256>>>(esrc, edst, dist, swp);

    // ---- layer 0 ----
    k_edgeT0<<<NBK, 256>>>();
    k_hgemmE<<<MB, 256>>>(Ah, Vh0, z16h, Ws0h, bs0, zi, KT0, 32);
    k_onsite3<0><<<MB, 256, ONSITE_SMEM>>>(zi,
        Wah + 0*3*DIM*DIM, bon_a + 0*3*DIM, Wbh + 0*3*DIM*DIM, bon_b + 0*3*DIM,
        zi, zih, out);

    // ---- layer 1 ----
    k_edgeT1<<<NBK, 256>>>();
    k_hgemmE<<<MB, 256>>>(Ah, Vh1, zih, Ws1h, bs1, zi, KT1, DIM);
    k_onsite3<1><<<MB, 256, ONSITE_SMEM>>>(zi,
        Wah + 1*3*DIM*DIM, bon_a + 1*3*DIM, Wbh + 1*3*DIM*DIM, bon_b + 1*3*DIM,
        zi, zih, out);
}